// round 1
// baseline (speedup 1.0000x reference)
#include <cuda_runtime.h>
#include <math.h>

#define NR 4096
#define MAXS 128

// ---------------- scratch (device globals; allocation-free rule) ----------------
__device__ float g_z[NR * MAXS];        // z_vals, row stride 128
__device__ float g_sdf[NR * MAXS];      // sdf at z_vals
__device__ float g_newz[NR * 16];       // new samples per upsample round
__device__ float g_newsdf[NR * 16];     // sdf at new samples
__device__ float g_pts[NR * MAXS * 3];  // MLP input points
__device__ float g_fsdf[NR * MAXS];     // final sdf at mid points
__device__ float g_tc[NR * MAXS];       // true_cos = dot(dir, grad)

__device__ __forceinline__ float softplusf(float x) {
    return fmaxf(x, 0.f) + log1pf(expf(-fabsf(x)));
}
__device__ __forceinline__ float sigmoidf(float x) {
    return 1.f / (1.f + expf(-x));
}

// ---------------- init z ----------------
__global__ void k_init_z(const float* __restrict__ near_, const float* __restrict__ far_) {
    int idx = blockIdx.x * blockDim.x + threadIdx.x;
    if (idx >= NR * 64) return;
    int r = idx >> 6, s = idx & 63;
    float t = (s == 63) ? 1.0f : s * (1.0f / 63.0f);
    g_z[r * MAXS + s] = near_[r] + (far_[r] - near_[r]) * t;
}

__global__ void k_gen_pts_init(const float* __restrict__ ro, const float* __restrict__ rd) {
    int idx = blockIdx.x * blockDim.x + threadIdx.x;
    if (idx >= NR * 64) return;
    int r = idx >> 6, s = idx & 63;
    float z = g_z[r * MAXS + s];
    g_pts[idx * 3 + 0] = ro[3 * r + 0] + rd[3 * r + 0] * z;
    g_pts[idx * 3 + 1] = ro[3 * r + 1] + rd[3 * r + 1] * z;
    g_pts[idx * 3 + 2] = ro[3 * r + 2] + rd[3 * r + 2] * z;
}

__global__ void k_gen_pts_new(const float* __restrict__ ro, const float* __restrict__ rd) {
    int idx = blockIdx.x * blockDim.x + threadIdx.x;
    if (idx >= NR * 16) return;
    int r = idx >> 4;
    float z = g_newz[idx];
    g_pts[idx * 3 + 0] = ro[3 * r + 0] + rd[3 * r + 0] * z;
    g_pts[idx * 3 + 1] = ro[3 * r + 1] + rd[3 * r + 1] * z;
    g_pts[idx * 3 + 2] = ro[3 * r + 2] + rd[3 * r + 2] * z;
}

__global__ void k_gen_pts_mid(const float* __restrict__ ro, const float* __restrict__ rd) {
    int idx = blockIdx.x * blockDim.x + threadIdx.x;
    if (idx >= NR * MAXS) return;
    int r = idx >> 7, s = idx & 127;
    float z = g_z[r * MAXS + s];
    float dist = (s < 127) ? (g_z[r * MAXS + s + 1] - z) : 0.03125f;  // SAMPLE_DIST = 2/64
    float mid = z + 0.5f * dist;
    g_pts[idx * 3 + 0] = ro[3 * r + 0] + rd[3 * r + 0] * mid;
    g_pts[idx * 3 + 1] = ro[3 * r + 1] + rd[3 * r + 1] * mid;
    g_pts[idx * 3 + 2] = ro[3 * r + 2] + rd[3 * r + 2] * mid;
}

// ---------------- MLP forward (thread per point, h1 in regs, W2^T in smem) ----------------
// smem layout: W2T[128*132] | W1s[384] | b1s[128] | b2s[128] | W3s[128]
#define SMEM_FWD ((128 * 132 + 384 + 128 + 128 + 128) * 4)

__global__ __launch_bounds__(128, 1) void k_mlp_fwd(
    const float* __restrict__ W1, const float* __restrict__ b1,
    const float* __restrict__ W2, const float* __restrict__ b2,
    const float* __restrict__ W3, const float* __restrict__ b3,
    int B, int mode)  // mode 0: init -> g_sdf[(b>>6)*128 + (b&63)]; mode 1: new -> g_newsdf[b]
{
    extern __shared__ float sm[];
    float* W2T = sm;
    float* W1s = sm + 128 * 132;
    float* b1s = W1s + 384;
    float* b2s = b1s + 128;
    float* W3s = b2s + 128;
    int t = threadIdx.x;
    #pragma unroll 4
    for (int k = 0; k < 128; k++) W2T[t * 132 + k] = W2[k * 128 + t];  // W2T[j][i] = W2[i][j]
    W1s[t] = W1[t]; W1s[128 + t] = W1[128 + t]; W1s[256 + t] = W1[256 + t];
    b1s[t] = b1[t]; b2s[t] = b2[t]; W3s[t] = W3[t];
    __syncthreads();

    int b = blockIdx.x * 128 + t;
    if (b >= B) return;
    float x = g_pts[3 * b], y = g_pts[3 * b + 1], zc = g_pts[3 * b + 2];

    float h1[128];
    #pragma unroll
    for (int i = 0; i < 128; i++) {
        float a = fmaf(x, W1s[i], fmaf(y, W1s[128 + i], fmaf(zc, W1s[256 + i], b1s[i])));
        h1[i] = softplusf(a);
    }
    float acc = b3[0];
    #pragma unroll 2
    for (int j = 0; j < 128; j++) {
        float a0 = b2s[j], a1 = 0.f, a2 = 0.f, a3 = 0.f;
        const float4* wr = (const float4*)(W2T + j * 132);
        #pragma unroll
        for (int q = 0; q < 32; q++) {
            float4 w = wr[q];
            a0 = fmaf(h1[4 * q + 0], w.x, a0);
            a1 = fmaf(h1[4 * q + 1], w.y, a1);
            a2 = fmaf(h1[4 * q + 2], w.z, a2);
            a3 = fmaf(h1[4 * q + 3], w.w, a3);
        }
        float a = (a0 + a1) + (a2 + a3);
        acc = fmaf(softplusf(a), W3s[j], acc);
    }
    if (mode == 0) g_sdf[(b >> 6) * MAXS + (b & 63)] = acc;
    else           g_newsdf[b] = acc;
}

// ---------------- MLP forward + backward (final render points) ----------------
// smem: W2T[128*132] | W2r[128*132] | g2s[128*129] | W1s[384] | b1s[128] | b2s[128] | W3s[128]
#define SMEM_BWD ((128 * 132 * 2 + 128 * 129 + 384 + 128 + 128 + 128) * 4)

__global__ __launch_bounds__(128, 1) void k_mlp_fwdbwd(
    const float* __restrict__ W1, const float* __restrict__ b1,
    const float* __restrict__ W2, const float* __restrict__ b2,
    const float* __restrict__ W3, const float* __restrict__ b3,
    const float* __restrict__ rd, float* __restrict__ grad_out)
{
    extern __shared__ float sm[];
    float* W2T = sm;                   // [j*132 + i]
    float* W2r = sm + 128 * 132;       // [i*132 + j]
    float* g2s = sm + 2 * 128 * 132;   // per-thread row, stride 129
    float* W1s = g2s + 128 * 129;
    float* b1s = W1s + 384;
    float* b2s = b1s + 128;
    float* W3s = b2s + 128;
    int t = threadIdx.x;
    #pragma unroll 4
    for (int k = 0; k < 128; k++) {
        float v = W2[k * 128 + t];
        W2T[t * 132 + k] = v;   // wrong orientation for this element? no:
        // W2T[j=t][i=k] needs W2[i=k][j=t] = W2[k*128+t]  ✓
        W2r[k * 132 + t] = v;   // W2r[i=k][j=t] = W2[k*128+t]             ✓
    }
    W1s[t] = W1[t]; W1s[128 + t] = W1[128 + t]; W1s[256 + t] = W1[256 + t];
    b1s[t] = b1[t]; b2s[t] = b2[t]; W3s[t] = W3[t];
    __syncthreads();

    int b = blockIdx.x * 128 + t;
    float x = g_pts[3 * b], y = g_pts[3 * b + 1], zc = g_pts[3 * b + 2];

    // pass A: forward, produce sdf and g2[j] = sigmoid(a2_j) * W3[j]
    float h1[128];
    #pragma unroll
    for (int i = 0; i < 128; i++) {
        float a = fmaf(x, W1s[i], fmaf(y, W1s[128 + i], fmaf(zc, W1s[256 + i], b1s[i])));
        h1[i] = softplusf(a);
    }
    float sdf = b3[0];
    float* myg2 = g2s + t * 129;
    #pragma unroll 2
    for (int j = 0; j < 128; j++) {
        float a0 = b2s[j], a1 = 0.f, a2 = 0.f, a3 = 0.f;
        const float4* wr = (const float4*)(W2T + j * 132);
        #pragma unroll
        for (int q = 0; q < 32; q++) {
            float4 w = wr[q];
            a0 = fmaf(h1[4 * q + 0], w.x, a0);
            a1 = fmaf(h1[4 * q + 1], w.y, a1);
            a2 = fmaf(h1[4 * q + 2], w.z, a2);
            a3 = fmaf(h1[4 * q + 3], w.w, a3);
        }
        float a = (a0 + a1) + (a2 + a3);
        float e = expf(-fabsf(a));
        float h2 = fmaxf(a, 0.f) + log1pf(e);
        float sig = (a >= 0.f) ? (1.f / (1.f + e)) : (e / (1.f + e));
        sdf = fmaf(h2, W3s[j], sdf);
        myg2[j] = sig * W3s[j];
    }
    g_fsdf[b] = sdf;

    // pass B: g1_i = sum_j W2[i][j]*g2[j];  grad = W1 @ (sigmoid(a1) * g1)
    float gx = 0.f, gy = 0.f, gz = 0.f;
    #pragma unroll 2
    for (int i = 0; i < 128; i++) {
        float a1v = fmaf(x, W1s[i], fmaf(y, W1s[128 + i], fmaf(zc, W1s[256 + i], b1s[i])));
        float s1 = 1.f / (1.f + expf(-a1v));
        float g0 = 0.f, g1a = 0.f, g2a = 0.f, g3 = 0.f;
        const float4* wr = (const float4*)(W2r + i * 132);
        #pragma unroll
        for (int q = 0; q < 32; q++) {
            float4 w = wr[q];
            g0  = fmaf(w.x, myg2[4 * q + 0], g0);
            g1a = fmaf(w.y, myg2[4 * q + 1], g1a);
            g2a = fmaf(w.z, myg2[4 * q + 2], g2a);
            g3  = fmaf(w.w, myg2[4 * q + 3], g3);
        }
        float gi = ((g0 + g1a) + (g2a + g3)) * s1;
        gx = fmaf(W1s[i], gi, gx);
        gy = fmaf(W1s[128 + i], gi, gy);
        gz = fmaf(W1s[256 + i], gi, gz);
    }
    grad_out[3 * b + 0] = gx;
    grad_out[3 * b + 1] = gy;
    grad_out[3 * b + 2] = gz;
    int rr = b >> 7;
    g_tc[b] = gx * rd[3 * rr] + gy * rd[3 * rr + 1] + gz * rd[3 * rr + 2];
}

// ---------------- per-ray upsample + sample_pdf ----------------
__global__ void k_upsample(int S, float inv_s,
                           const float* __restrict__ ro, const float* __restrict__ rd) {
    int r = blockIdx.x * blockDim.x + threadIdx.x;
    if (r >= NR) return;
    float ox = ro[3 * r], oy = ro[3 * r + 1], oz = ro[3 * r + 2];
    float dx = rd[3 * r], dy = rd[3 * r + 1], dz = rd[3 * r + 2];
    float z[112], f[112], w[111], cdf[112];
    for (int k = 0; k < S; k++) { z[k] = g_z[r * MAXS + k]; f[k] = g_sdf[r * MAXS + k]; }

    float T = 1.f, wsum = 0.f, cprev = 0.f;
    float px = ox + dx * z[0], py = oy + dy * z[0], pz = oz + dz * z[0];
    float rad_prev = sqrtf(px * px + py * py + pz * pz);
    for (int k = 0; k < S - 1; k++) {
        float zb = z[k + 1];
        float qx = ox + dx * zb, qy = oy + dy * zb, qz = oz + dz * zb;
        float rad_next = sqrtf(qx * qx + qy * qy + qz * qz);
        float inside = (rad_prev < 1.f || rad_next < 1.f) ? 1.f : 0.f;
        rad_prev = rad_next;
        float c = (f[k + 1] - f[k]) / (z[k + 1] - z[k] + 1e-5f);
        float cc = fminf((k == 0) ? 0.f : cprev, c);
        cprev = c;
        cc = fminf(fmaxf(cc, -1000.f), 0.f) * inside;
        float mid = 0.5f * (f[k] + f[k + 1]);
        float dist = z[k + 1] - z[k];
        float pc = sigmoidf((mid - cc * dist * 0.5f) * inv_s);
        float nc = sigmoidf((mid + cc * dist * 0.5f) * inv_s);
        float a = (pc - nc + 1e-5f) / (pc + 1e-5f);
        float wk = a * T + 1e-5f;   // sample_pdf adds 1e-5
        T *= (1.f - a + 1e-7f);
        w[k] = wk; wsum += wk;
    }
    cdf[0] = 0.f;
    float run = 0.f;
    for (int k = 0; k < S - 1; k++) { run += w[k] / wsum; cdf[k + 1] = run; }

    const float du = (0.9375f - 0.03125f) / 15.f;
    int idx = 0;
    for (int t = 0; t < 16; t++) {
        float u = (t == 15) ? 0.96875f : (0.03125f + t * du);
        while (idx < S && cdf[idx] <= u) idx++;   // searchsorted side='right'
        int below = max(idx - 1, 0), above = min(idx, S - 1);
        float cb = cdf[below], ca = cdf[above];
        float denom = ca - cb;
        if (denom < 1e-5f) denom = 1.f;
        float tt = (u - cb) / denom;
        g_newz[r * 16 + t] = z[below] + tt * (z[above] - z[below]);
    }
}

// ---------------- per-ray stable merge (old before new on ties, matching stable argsort) --
__global__ void k_merge(int S, int last) {
    int r = blockIdx.x * blockDim.x + threadIdx.x;
    if (r >= NR) return;
    float zt[128], st[128];
    int i = 0, j = 0;
    for (int t = 0; t < S + 16; t++) {
        bool takeold;
        if (i >= S) takeold = false;
        else if (j >= 16) takeold = true;
        else takeold = (g_z[r * MAXS + i] <= g_newz[r * 16 + j]);
        if (takeold) {
            zt[t] = g_z[r * MAXS + i];
            if (!last) st[t] = g_sdf[r * MAXS + i];
            i++;
        } else {
            zt[t] = g_newz[r * 16 + j];
            if (!last) st[t] = g_newsdf[r * 16 + j];
            j++;
        }
    }
    for (int t = 0; t < S + 16; t++) {
        g_z[r * MAXS + t] = zt[t];
        if (!last) g_sdf[r * MAXS + t] = st[t];
    }
}

// ---------------- per-ray render (depth) ----------------
__global__ void k_render(const float* __restrict__ variance, float* __restrict__ out) {
    int r = blockIdx.x * blockDim.x + threadIdx.x;
    if (r >= NR) return;
    float inv_s = expf(10.f * variance[0]);
    inv_s = fminf(fmaxf(inv_s, 1e-6f), 1e6f);
    float T = 1.f, depth = 0.f;
    for (int k = 0; k < 128; k++) {
        float zk = g_z[r * MAXS + k];
        float dist = (k < 127) ? (g_z[r * MAXS + k + 1] - zk) : 0.03125f;
        float tc = g_tc[r * MAXS + k];
        float itc = -fmaxf(0.5f - 0.5f * tc, 0.f);   // COS_ANNEAL_RATIO = 0
        float sdf = g_fsdf[r * MAXS + k];
        float pc = sigmoidf((sdf - itc * dist * 0.5f) * inv_s);
        float nc = sigmoidf((sdf + itc * dist * 0.5f) * inv_s);
        float a = (pc - nc + 1e-5f) / (pc + 1e-5f);
        a = fminf(fmaxf(a, 0.f), 1.f);
        depth += a * T * zk;
        T *= (1.f - a + 1e-7f);
    }
    out[r] = depth;
}

// ---------------- launch ----------------
extern "C" void kernel_launch(void* const* d_in, const int* in_sizes, int n_in,
                              void* d_out, int out_size) {
    const float* rays_o = (const float*)d_in[0];
    const float* rays_d = (const float*)d_in[1];
    const float* near_  = (const float*)d_in[2];
    const float* far_   = (const float*)d_in[3];
    const float* W1 = (const float*)d_in[4];
    const float* b1 = (const float*)d_in[5];
    const float* W2 = (const float*)d_in[6];
    const float* b2 = (const float*)d_in[7];
    const float* W3 = (const float*)d_in[8];
    const float* b3 = (const float*)d_in[9];
    const float* var = (const float*)d_in[10];
    float* out = (float*)d_out;

    cudaFuncSetAttribute(k_mlp_fwd, cudaFuncAttributeMaxDynamicSharedMemorySize, SMEM_FWD);
    cudaFuncSetAttribute(k_mlp_fwdbwd, cudaFuncAttributeMaxDynamicSharedMemorySize, SMEM_BWD);

    // initial coarse sampling: S=64
    k_init_z<<<(NR * 64) / 256, 256>>>(near_, far_);
    k_gen_pts_init<<<(NR * 64) / 256, 256>>>(rays_o, rays_d);
    k_mlp_fwd<<<(NR * 64) / 128, 128, SMEM_FWD>>>(W1, b1, W2, b2, W3, b3, NR * 64, 0);

    // 4 upsample rounds, +16 samples each
    for (int i = 0; i < 4; i++) {
        int S = 64 + 16 * i;
        float inv_s = (float)(64 << i);
        k_upsample<<<NR / 128, 128>>>(S, inv_s, rays_o, rays_d);
        if (i < 3) {
            k_gen_pts_new<<<(NR * 16) / 256, 256>>>(rays_o, rays_d);
            k_mlp_fwd<<<(NR * 16) / 128, 128, SMEM_FWD>>>(W1, b1, W2, b2, W3, b3, NR * 16, 1);
        }
        k_merge<<<NR / 128, 128>>>(S, (i == 3) ? 1 : 0);
    }

    // final render: S=128, fused forward+backward MLP, gradients straight to output
    k_gen_pts_mid<<<(NR * 128) / 256, 256>>>(rays_o, rays_d);
    k_mlp_fwdbwd<<<NR, 128, SMEM_BWD>>>(W1, b1, W2, b2, W3, b3, rays_d, out + NR);
    k_render<<<NR / 128, 128>>>(var, out);
}

// round 2
// speedup vs baseline: 1.2464x; 1.2464x over previous
#include <cuda_runtime.h>
#include <math.h>

#define NR 4096
#define MAXS 128
typedef unsigned long long ull;

// ---------------- scratch (device globals) ----------------
__device__ float g_z0[NR * MAXS], g_z1[NR * MAXS];   // z ping-pong, layout [s][r]
__device__ float g_s0[NR * MAXS], g_s1[NR * MAXS];   // sdf ping-pong
__device__ float g_newz[NR * 16], g_newsdf[NR * 16]; // [t][r]
__device__ float g_w[NR * MAXS];                     // upsample weights scratch
__device__ float g_fsdf[NR * MAXS], g_tc[NR * MAXS]; // final pass, [s][r]

// ---------------- helpers ----------------
__device__ __forceinline__ ull pack2(float lo, float hi) {
    ull d; asm("mov.b64 %0, {%1, %2};" : "=l"(d) : "f"(lo), "f"(hi)); return d;
}
__device__ __forceinline__ void unpack2(ull v, float& lo, float& hi) {
    asm("mov.b64 {%0, %1}, %2;" : "=f"(lo), "=f"(hi) : "l"(v));
}
__device__ __forceinline__ ull ffma2(ull a, ull b, ull c) {
    ull d; asm("fma.rn.f32x2 %0, %1, %2, %3;" : "=l"(d) : "l"(a), "l"(b), "l"(c)); return d;
}
__device__ __forceinline__ ull fadd2(ull a, ull b) {
    ull d; asm("add.rn.f32x2 %0, %1, %2;" : "=l"(d) : "l"(a), "l"(b)); return d;
}
__device__ __forceinline__ float softplusf(float x) {
    return fmaxf(x, 0.f) + log1pf(expf(-fabsf(x)));
}
__device__ __forceinline__ float sigmoidf(float x) {
    return 1.f / (1.f + expf(-x));
}

// ---------------- init z (linspace, [s][r]) ----------------
__global__ void k_init_z(const float* __restrict__ near_, const float* __restrict__ far_) {
    int idx = blockIdx.x * blockDim.x + threadIdx.x;
    if (idx >= NR * 64) return;
    int r = idx & (NR - 1), s = idx >> 12;
    float t = (s == 63) ? 1.0f : s * (1.0f / 63.0f);
    g_z0[s * NR + r] = near_[r] + (far_[r] - near_[r]) * t;
}

// ---------------- MLP forward core (packed f32x2) ----------------
// smem: W2T[128*132] | (g2s for bwd) | W1s[384] | b1s[128] | b2s[128] | W3s[128]
#define SMEM_FWD ((128 * 132 + 384 + 128 + 128 + 128) * 4)
#define SMEM_BWD ((128 * 132 + 256 * 129 + 384 + 128 + 128 + 128) * 4)

// computes sdf; if g2row != nullptr also writes g2[j] = sigmoid(a2_j)*W3[j]
template <bool WG2>
__device__ __forceinline__ float mlp_forward(
    float x, float y, float zc,
    const float* W2T, const float* W1s, const float* b1s,
    const float* b2s, const float* W3s, float b3v,
    ull* h1p, float* g2row)
{
    const ull* W1p = (const ull*)W1s;
    const ull* b1p = (const ull*)b1s;
    ull xx = pack2(x, x), yy = pack2(y, y), zz = pack2(zc, zc);
    #pragma unroll
    for (int k = 0; k < 64; k++) {
        ull a = ffma2(xx, W1p[k], ffma2(yy, W1p[64 + k], ffma2(zz, W1p[128 + k], b1p[k])));
        float lo, hi; unpack2(a, lo, hi);
        h1p[k] = pack2(softplusf(lo), softplusf(hi));
    }
    float sdf = b3v;
    #pragma unroll 2
    for (int j = 0; j < 128; j++) {
        const ulonglong2* wp = (const ulonglong2*)(W2T + j * 132);
        ull aA = pack2(b2s[j], 0.f), aB = 0, aC = 0, aD = 0;
        #pragma unroll
        for (int q = 0; q < 32; q += 2) {
            ulonglong2 w0 = wp[q];
            ulonglong2 w1 = wp[q + 1];
            aA = ffma2(h1p[2 * q], w0.x, aA);
            aB = ffma2(h1p[2 * q + 1], w0.y, aB);
            aC = ffma2(h1p[2 * q + 2], w1.x, aC);
            aD = ffma2(h1p[2 * q + 3], w1.y, aD);
        }
        ull s = fadd2(fadd2(aA, aC), fadd2(aB, aD));
        float lo, hi; unpack2(s, lo, hi);
        float a = lo + hi;
        float e = expf(-fabsf(a));
        float h2 = fmaxf(a, 0.f) + log1pf(e);
        sdf = fmaf(h2, W3s[j], sdf);
        if (WG2) {
            float sig = (a >= 0.f) ? (1.f / (1.f + e)) : (e / (1.f + e));
            g2row[j] = sig * W3s[j];
        }
    }
    return sdf;
}

__device__ __forceinline__ void load_weights_smem(
    float* W2T, float* W1s, float* b1s, float* b2s, float* W3s,
    const float* W1, const float* b1, const float* W2,
    const float* b2, const float* W3, int t, int nthr)
{
    for (int idx = t; idx < 16384; idx += nthr) {
        int i = idx >> 7, j = idx & 127;
        W2T[j * 132 + i] = W2[i * 128 + j];
    }
    for (int idx = t; idx < 384; idx += nthr) W1s[idx] = W1[idx];
    for (int idx = t; idx < 128; idx += nthr) {
        b1s[idx] = b1[idx]; b2s[idx] = b2[idx]; W3s[idx] = W3[idx];
    }
}

// ---------------- forward-only MLP kernel ----------------
__global__ __launch_bounds__(256, 1) void k_mlp_fwd(
    const float* __restrict__ W1, const float* __restrict__ b1,
    const float* __restrict__ W2, const float* __restrict__ b2,
    const float* __restrict__ W3, const float* __restrict__ b3,
    const float* __restrict__ ro, const float* __restrict__ rd,
    int mode)  // 0: init samples (s<64, z from g_z0) -> g_s0; 1: new samples -> g_newsdf
{
    extern __shared__ float sm[];
    float* W2T = sm;
    float* W1s = sm + 128 * 132;
    float* b1s = W1s + 384; float* b2s = b1s + 128; float* W3s = b2s + 128;
    int t = threadIdx.x;
    load_weights_smem(W2T, W1s, b1s, b2s, W3s, W1, b1, W2, b2, W3, t, 256);
    __syncthreads();

    int idx = blockIdx.x * 256 + t;
    int r = idx & (NR - 1), s = idx >> 12;
    float z = (mode == 0) ? g_z0[s * NR + r] : g_newz[s * NR + r];
    float x = ro[3 * r] + rd[3 * r] * z;
    float y = ro[3 * r + 1] + rd[3 * r + 1] * z;
    float zc = ro[3 * r + 2] + rd[3 * r + 2] * z;

    ull h1p[64];
    float sdf = mlp_forward<false>(x, y, zc, W2T, W1s, b1s, b2s, W3s, b3[0], h1p, nullptr);
    if (mode == 0) g_s0[s * NR + r] = sdf;
    else           g_newsdf[s * NR + r] = sdf;
}

// ---------------- fused forward + backward (final render points) ----------------
__global__ __launch_bounds__(256, 1) void k_mlp_fwdbwd(
    const float* __restrict__ W1, const float* __restrict__ b1,
    const float* __restrict__ W2, const float* __restrict__ b2,
    const float* __restrict__ W3, const float* __restrict__ b3,
    const float* __restrict__ ro, const float* __restrict__ rd,
    float* __restrict__ grad_out)
{
    extern __shared__ float sm[];
    float* W2T = sm;
    float* g2s = sm + 128 * 132;             // 256 rows, stride 129 (conflict-free)
    float* W1s = g2s + 256 * 129;
    float* b1s = W1s + 384; float* b2s = b1s + 128; float* W3s = b2s + 128;
    int t = threadIdx.x;
    load_weights_smem(W2T, W1s, b1s, b2s, W3s, W1, b1, W2, b2, W3, t, 256);
    __syncthreads();

    int idx = blockIdx.x * 256 + t;
    int r = idx & (NR - 1), s = idx >> 12;
    float zk = g_z0[s * NR + r];
    float dist = (s < 127) ? (g_z0[(s + 1) * NR + r] - zk) : 0.03125f;  // SAMPLE_DIST
    float mid = zk + 0.5f * dist;
    float dx = rd[3 * r], dy = rd[3 * r + 1], dz = rd[3 * r + 2];
    float x = ro[3 * r] + dx * mid;
    float y = ro[3 * r + 1] + dy * mid;
    float zc = ro[3 * r + 2] + dz * mid;
    float* g2row = g2s + t * 129;

    // pass A: forward, sdf + g2
    {
        ull h1p[64];
        float sdf = mlp_forward<true>(x, y, zc, W2T, W1s, b1s, b2s, W3s, b3[0], h1p, g2row);
        g_fsdf[s * NR + r] = sdf;
    }

    // pass B: g1 = W2 @ g2 (packed over i-pairs, W2T broadcast reads)
    {
        ull gp[64];
        #pragma unroll
        for (int k = 0; k < 64; k++) gp[k] = 0;
        for (int j = 0; j < 128; j++) {
            float g2v = g2row[j];
            ull g2p = pack2(g2v, g2v);
            const ulonglong2* wp = (const ulonglong2*)(W2T + j * 132);
            #pragma unroll
            for (int q = 0; q < 32; q++) {
                ulonglong2 w = wp[q];
                gp[2 * q]     = ffma2(w.x, g2p, gp[2 * q]);
                gp[2 * q + 1] = ffma2(w.y, g2p, gp[2 * q + 1]);
            }
        }
        // stash g1 into own smem row (frees the register array for the rolled epilogue)
        #pragma unroll
        for (int k = 0; k < 64; k++) {
            float lo, hi; unpack2(gp[k], lo, hi);
            g2row[2 * k] = lo; g2row[2 * k + 1] = hi;
        }
    }

    // epilogue: grad = W1 @ (sigmoid(a1) * g1)
    const ull* W1p = (const ull*)W1s;
    const ull* b1p = (const ull*)b1s;
    ull xx = pack2(x, x), yy = pack2(y, y), zz = pack2(zc, zc);
    ull gxp = 0, gyp = 0, gzp = 0;
    for (int k = 0; k < 64; k++) {
        ull w1a = W1p[k], w1b = W1p[64 + k], w1c = W1p[128 + k];
        ull a1 = ffma2(xx, w1a, ffma2(yy, w1b, ffma2(zz, w1c, b1p[k])));
        float alo, ahi; unpack2(a1, alo, ahi);
        float s1lo = sigmoidf(alo), s1hi = sigmoidf(ahi);
        ull gi = pack2(g2row[2 * k] * s1lo, g2row[2 * k + 1] * s1hi);
        gxp = ffma2(w1a, gi, gxp);
        gyp = ffma2(w1b, gi, gyp);
        gzp = ffma2(w1c, gi, gzp);
    }
    float gx, gy, gz, tmp0, tmp1;
    unpack2(gxp, tmp0, tmp1); gx = tmp0 + tmp1;
    unpack2(gyp, tmp0, tmp1); gy = tmp0 + tmp1;
    unpack2(gzp, tmp0, tmp1); gz = tmp0 + tmp1;

    int p = r * 128 + s;
    grad_out[3 * p + 0] = gx;
    grad_out[3 * p + 1] = gy;
    grad_out[3 * p + 2] = gz;
    g_tc[s * NR + r] = gx * dx + gy * dy + gz * dz;
}

// ---------------- per-ray upsample + sample_pdf (coalesced, no local arrays) ----
__global__ void k_upsample(int S, float inv_s, int flag,
                           const float* __restrict__ ro, const float* __restrict__ rd) {
    int r = blockIdx.x * blockDim.x + threadIdx.x;
    if (r >= NR) return;
    const float* zb = flag ? g_z1 : g_z0;
    const float* fb = flag ? g_s1 : g_s0;
    float ox = ro[3 * r], oy = ro[3 * r + 1], oz = ro[3 * r + 2];
    float dx = rd[3 * r], dy = rd[3 * r + 1], dz = rd[3 * r + 2];

    // pass 1: weights -> g_w, wsum
    float T = 1.f, wsum = 0.f, cprev = 0.f;
    float z0v = zb[r], f0 = fb[r];
    float px = ox + dx * z0v, py = oy + dy * z0v, pz = oz + dz * z0v;
    float rad_prev = sqrtf(px * px + py * py + pz * pz);
    for (int k = 0; k < S - 1; k++) {
        float z1v = zb[(k + 1) * NR + r], f1 = fb[(k + 1) * NR + r];
        float qx = ox + dx * z1v, qy = oy + dy * z1v, qz = oz + dz * z1v;
        float rad_next = sqrtf(qx * qx + qy * qy + qz * qz);
        float inside = (rad_prev < 1.f || rad_next < 1.f) ? 1.f : 0.f;
        rad_prev = rad_next;
        float c = (f1 - f0) / (z1v - z0v + 1e-5f);
        float cc = fminf((k == 0) ? 0.f : cprev, c);
        cprev = c;
        cc = fminf(fmaxf(cc, -1000.f), 0.f) * inside;
        float midv = 0.5f * (f0 + f1);
        float dd = z1v - z0v;
        float pc = sigmoidf((midv - cc * dd * 0.5f) * inv_s);
        float nc = sigmoidf((midv + cc * dd * 0.5f) * inv_s);
        float a = (pc - nc + 1e-5f) / (pc + 1e-5f);
        float wk = a * T + 1e-5f;   // sample_pdf adds 1e-5
        T *= (1.f - a + 1e-7f);
        g_w[k * NR + r] = wk;
        wsum += wk;
        z0v = z1v; f0 = f1;
    }

    // pass 2: cdf walk + inverse-CDF sampling (searchsorted side='right' semantics)
    int t = 0;
    float cb = 0.f, run = 0.f;
    z0v = zb[r];
    for (int k = 0; k < S - 1 && t < 16; k++) {
        float z1v = zb[(k + 1) * NR + r];
        run += g_w[k * NR + r] / wsum;
        while (t < 16) {
            float u = (float)(2 * t + 1) * 0.03125f;   // exact (2t+1)/32
            if (!(u < run)) break;
            float denom = run - cb;
            if (denom < 1e-5f) denom = 1.f;
            float tt = (u - cb) / denom;
            g_newz[t * NR + r] = z0v + tt * (z1v - z0v);
            t++;
        }
        cb = run; z0v = z1v;
    }
    float zlast = zb[(S - 1) * NR + r];
    while (t < 16) { g_newz[t * NR + r] = zlast; t++; }
}

// ---------------- per-ray stable merge (streaming, ping-pong) ----------------
__global__ void k_merge(int S, int flag, int last) {
    int r = blockIdx.x * blockDim.x + threadIdx.x;
    if (r >= NR) return;
    const float* zi = flag ? g_z1 : g_z0;
    float* zo = flag ? g_z0 : g_z1;
    const float* si = flag ? g_s1 : g_s0;
    float* so = flag ? g_s0 : g_s1;
    int i = 0, j = 0;
    float zv = zi[r], nv = g_newz[r];
    for (int t = 0; t < S + 16; t++) {
        bool takeold = (j >= 16) || (i < S && zv <= nv);
        if (takeold) {
            zo[t * NR + r] = zv;
            if (!last) so[t * NR + r] = si[i * NR + r];
            i++;
            if (i < S) zv = zi[i * NR + r];
        } else {
            zo[t * NR + r] = nv;
            if (!last) so[t * NR + r] = g_newsdf[j * NR + r];
            j++;
            if (j < 16) nv = g_newz[j * NR + r];
        }
    }
}

// ---------------- per-ray render (depth) ----------------
__global__ void k_render(const float* __restrict__ variance, float* __restrict__ out) {
    int r = blockIdx.x * blockDim.x + threadIdx.x;
    if (r >= NR) return;
    float inv_s = expf(10.f * variance[0]);
    inv_s = fminf(fmaxf(inv_s, 1e-6f), 1e6f);
    float T = 1.f, depth = 0.f;
    for (int k = 0; k < 128; k++) {
        float zk = g_z0[k * NR + r];
        float dist = (k < 127) ? (g_z0[(k + 1) * NR + r] - zk) : 0.03125f;
        float tc = g_tc[k * NR + r];
        float itc = -fmaxf(0.5f - 0.5f * tc, 0.f);   // COS_ANNEAL_RATIO = 0
        float sdf = g_fsdf[k * NR + r];
        float pc = sigmoidf((sdf - itc * dist * 0.5f) * inv_s);
        float nc = sigmoidf((sdf + itc * dist * 0.5f) * inv_s);
        float a = (pc - nc + 1e-5f) / (pc + 1e-5f);
        a = fminf(fmaxf(a, 0.f), 1.f);
        depth += a * T * zk;
        T *= (1.f - a + 1e-7f);
    }
    out[r] = depth;
}

// ---------------- launch ----------------
extern "C" void kernel_launch(void* const* d_in, const int* in_sizes, int n_in,
                              void* d_out, int out_size) {
    const float* rays_o = (const float*)d_in[0];
    const float* rays_d = (const float*)d_in[1];
    const float* near_  = (const float*)d_in[2];
    const float* far_   = (const float*)d_in[3];
    const float* W1 = (const float*)d_in[4];
    const float* b1 = (const float*)d_in[5];
    const float* W2 = (const float*)d_in[6];
    const float* b2 = (const float*)d_in[7];
    const float* W3 = (const float*)d_in[8];
    const float* b3 = (const float*)d_in[9];
    const float* var = (const float*)d_in[10];
    float* out = (float*)d_out;

    cudaFuncSetAttribute(k_mlp_fwd, cudaFuncAttributeMaxDynamicSharedMemorySize, SMEM_FWD);
    cudaFuncSetAttribute(k_mlp_fwdbwd, cudaFuncAttributeMaxDynamicSharedMemorySize, SMEM_BWD);

    // initial coarse sampling: S=64
    k_init_z<<<(NR * 64) / 256, 256>>>(near_, far_);
    k_mlp_fwd<<<(NR * 64) / 256, 256, SMEM_FWD>>>(W1, b1, W2, b2, W3, b3, rays_o, rays_d, 0);

    // 4 upsample rounds, +16 samples each; z/sdf ping-pong (round i reads buf i&1)
    for (int i = 0; i < 4; i++) {
        int S = 64 + 16 * i;
        float inv_s = (float)(64 << i);
        int flag = i & 1;
        k_upsample<<<NR / 64, 64>>>(S, inv_s, flag, rays_o, rays_d);
        if (i < 3)
            k_mlp_fwd<<<(NR * 16) / 256, 256, SMEM_FWD>>>(W1, b1, W2, b2, W3, b3, rays_o, rays_d, 1);
        k_merge<<<NR / 128, 128>>>(S, flag, (i == 3) ? 1 : 0);
    }

    // final: S=128 (in g_z0), fused forward+backward MLP, then render
    k_mlp_fwdbwd<<<(NR * 128) / 256, 256, SMEM_BWD>>>(W1, b1, W2, b2, W3, b3,
                                                      rays_o, rays_d, out + NR);
    k_render<<<NR / 128, 128>>>(var, out);
}

// round 6
// speedup vs baseline: 1.2764x; 1.0240x over previous
#include <cuda_runtime.h>
#include <math.h>

#define NR 4096
#define MAXS 128
typedef unsigned long long ull;

// ---------------- scratch (device globals) ----------------
__device__ float g_z0[NR * MAXS], g_z1[NR * MAXS];   // z ping-pong, layout [s][r]
__device__ float g_s0[NR * MAXS], g_s1[NR * MAXS];   // sdf ping-pong
__device__ float g_newz[NR * 16], g_newsdf[NR * 16]; // [t][r]
__device__ float g_w[NR * MAXS];                     // upsample weights scratch
__device__ float g_fsdf[NR * MAXS], g_tc[NR * MAXS]; // final pass, [s][r]

// ---------------- helpers ----------------
__device__ __forceinline__ ull pack2(float lo, float hi) {
    ull d; asm("mov.b64 %0, {%1, %2};" : "=l"(d) : "f"(lo), "f"(hi)); return d;
}
__device__ __forceinline__ void unpack2(ull v, float& lo, float& hi) {
    asm("mov.b64 {%0, %1}, %2;" : "=f"(lo), "=f"(hi) : "l"(v));
}
__device__ __forceinline__ ull ffma2(ull a, ull b, ull c) {
    ull d; asm("fma.rn.f32x2 %0, %1, %2, %3;" : "=l"(d) : "l"(a), "l"(b), "l"(c)); return d;
}
__device__ __forceinline__ ull fadd2(ull a, ull b) {
    ull d; asm("add.rn.f32x2 %0, %1, %2;" : "=l"(d) : "l"(a), "l"(b)); return d;
}
__device__ __forceinline__ float softplusf(float x) {
    return fmaxf(x, 0.f) + log1pf(expf(-fabsf(x)));
}
__device__ __forceinline__ float sigmoidf(float x) {
    return 1.f / (1.f + expf(-x));
}

// ---------------- init z (linspace, [s][r]) ----------------
__global__ void k_init_z(const float* __restrict__ near_, const float* __restrict__ far_) {
    int idx = blockIdx.x * blockDim.x + threadIdx.x;
    if (idx >= NR * 64) return;
    int r = idx & (NR - 1), s = idx >> 12;
    float t = (s == 63) ? 1.0f : s * (1.0f / 63.0f);
    g_z0[s * NR + r] = near_[r] + (far_[r] - near_[r]) * t;
}

// ---------------- MLP forward core (packed f32x2) ----------------
#define SMEM_FWD ((128 * 132 + 384 + 128 + 128 + 128) * 4)
#define SMEM_BWD ((128 * 132 + 256 * 129 + 384 + 128 + 128 + 128) * 4)

// computes sdf; if WG2 also writes g2[j] = sigmoid(a2_j)*W3[j] to g2row
template <bool WG2>
__device__ __forceinline__ float mlp_forward(
    float x, float y, float zc,
    const float* W2T, const float* W1s, const float* b1s,
    const float* b2s, const float* W3s, float b3v,
    ull* h1p, float* g2row)
{
    const ull* W1p = (const ull*)W1s;
    const ull* b1p = (const ull*)b1s;
    ull xx = pack2(x, x), yy = pack2(y, y), zz = pack2(zc, zc);
    #pragma unroll
    for (int k = 0; k < 64; k++) {
        ull a = ffma2(xx, W1p[k], ffma2(yy, W1p[64 + k], ffma2(zz, W1p[128 + k], b1p[k])));
        float lo, hi; unpack2(a, lo, hi);
        h1p[k] = pack2(softplusf(lo), softplusf(hi));
    }
    float sdf = b3v;
    #pragma unroll 2
    for (int j = 0; j < 128; j++) {
        const ulonglong2* wp = (const ulonglong2*)(W2T + j * 132);
        ull aA = pack2(b2s[j], 0.f), aB = 0, aC = 0, aD = 0;
        #pragma unroll
        for (int q = 0; q < 32; q += 2) {
            ulonglong2 w0 = wp[q];
            ulonglong2 w1 = wp[q + 1];
            aA = ffma2(h1p[2 * q], w0.x, aA);
            aB = ffma2(h1p[2 * q + 1], w0.y, aB);
            aC = ffma2(h1p[2 * q + 2], w1.x, aC);
            aD = ffma2(h1p[2 * q + 3], w1.y, aD);
        }
        ull s = fadd2(fadd2(aA, aC), fadd2(aB, aD));
        float lo, hi; unpack2(s, lo, hi);
        float a = lo + hi;
        float e = expf(-fabsf(a));
        float h2 = fmaxf(a, 0.f) + log1pf(e);
        sdf = fmaf(h2, W3s[j], sdf);
        if (WG2) {
            float sig = (a >= 0.f) ? (1.f / (1.f + e)) : (e / (1.f + e));
            g2row[j] = sig * W3s[j];
        }
    }
    return sdf;
}

__device__ __forceinline__ void load_weights_smem(
    float* W2T, float* W1s, float* b1s, float* b2s, float* W3s,
    const float* W1, const float* b1, const float* W2,
    const float* b2, const float* W3, int t, int nthr)
{
    for (int idx = t; idx < 16384; idx += nthr) {
        int i = idx >> 7, j = idx & 127;
        W2T[j * 132 + i] = W2[i * 128 + j];
    }
    for (int idx = t; idx < 384; idx += nthr) W1s[idx] = W1[idx];
    for (int idx = t; idx < 128; idx += nthr) {
        b1s[idx] = b1[idx]; b2s[idx] = b2[idx]; W3s[idx] = W3[idx];
    }
}

// ---------------- forward-only MLP kernel ----------------
__global__ __launch_bounds__(256, 1) void k_mlp_fwd(
    const float* __restrict__ W1, const float* __restrict__ b1,
    const float* __restrict__ W2, const float* __restrict__ b2,
    const float* __restrict__ W3, const float* __restrict__ b3,
    const float* __restrict__ ro, const float* __restrict__ rd,
    int mode)  // 0: init samples (z from g_z0) -> g_s0; 1: new samples -> g_newsdf
{
    extern __shared__ float sm[];
    float* W2T = sm;
    float* W1s = sm + 128 * 132;
    float* b1s = W1s + 384; float* b2s = b1s + 128; float* W3s = b2s + 128;
    int t = threadIdx.x;
    load_weights_smem(W2T, W1s, b1s, b2s, W3s, W1, b1, W2, b2, W3, t, 256);
    __syncthreads();

    int idx = blockIdx.x * 256 + t;
    int r = idx & (NR - 1), s = idx >> 12;
    float z = (mode == 0) ? g_z0[s * NR + r] : g_newz[s * NR + r];
    float x = ro[3 * r] + rd[3 * r] * z;
    float y = ro[3 * r + 1] + rd[3 * r + 1] * z;
    float zc = ro[3 * r + 2] + rd[3 * r + 2] * z;

    ull h1p[64];
    float sdf = mlp_forward<false>(x, y, zc, W2T, W1s, b1s, b2s, W3s, b3[0], h1p, nullptr);
    if (mode == 0) g_s0[s * NR + r] = sdf;
    else           g_newsdf[s * NR + r] = sdf;
}

// ---------------- fused forward + backward (final render points) ----------------
// Pass B restructured: backward i-range in two halves of 32 packed accumulators
// (64 regs), epilogue fused per half. Peak pass-B register pressure ~95 -> no spills.
__global__ __launch_bounds__(256, 1) void k_mlp_fwdbwd(
    const float* __restrict__ W1, const float* __restrict__ b1,
    const float* __restrict__ W2, const float* __restrict__ b2,
    const float* __restrict__ W3, const float* __restrict__ b3,
    const float* __restrict__ ro, const float* __restrict__ rd,
    float* __restrict__ grad_out)
{
    extern __shared__ float sm[];
    float* W2T = sm;
    float* g2s = sm + 128 * 132;             // 256 rows, stride 129 (conflict-free)
    float* W1s = g2s + 256 * 129;
    float* b1s = W1s + 384; float* b2s = b1s + 128; float* W3s = b2s + 128;
    int t = threadIdx.x;
    load_weights_smem(W2T, W1s, b1s, b2s, W3s, W1, b1, W2, b2, W3, t, 256);
    __syncthreads();

    int idx = blockIdx.x * 256 + t;
    int r = idx & (NR - 1), s = idx >> 12;
    float zk = g_z0[s * NR + r];
    float dist = (s < 127) ? (g_z0[(s + 1) * NR + r] - zk) : 0.03125f;  // SAMPLE_DIST
    float mid = zk + 0.5f * dist;
    float dx = rd[3 * r], dy = rd[3 * r + 1], dz = rd[3 * r + 2];
    float x = ro[3 * r] + dx * mid;
    float y = ro[3 * r + 1] + dy * mid;
    float zc = ro[3 * r + 2] + dz * mid;
    float* g2row = g2s + t * 129;

    // pass A: forward, sdf + g2
    {
        ull h1p[64];
        float sdf = mlp_forward<true>(x, y, zc, W2T, W1s, b1s, b2s, W3s, b3[0], h1p, g2row);
        g_fsdf[s * NR + r] = sdf;
    }

    // pass B: g1 = W2 @ g2, half the i-range at a time; epilogue fused per half.
    const ull* W1p = (const ull*)W1s;
    const ull* b1p = (const ull*)b1s;
    ull xx = pack2(x, x), yy = pack2(y, y), zz = pack2(zc, zc);
    ull gxp = 0, gyp = 0, gzp = 0;
    #pragma unroll 1
    for (int half = 0; half < 2; half++) {
        ull gp[32];
        #pragma unroll
        for (int k = 0; k < 32; k++) gp[k] = 0;
        #pragma unroll 1
        for (int j = 0; j < 128; j++) {
            float g2v = g2row[j];
            ull g2p = pack2(g2v, g2v);
            const ulonglong2* wp = (const ulonglong2*)(W2T + j * 132 + half * 64);
            #pragma unroll
            for (int q = 0; q < 16; q++) {
                ulonglong2 w = wp[q];
                gp[2 * q]     = ffma2(w.x, g2p, gp[2 * q]);
                gp[2 * q + 1] = ffma2(w.y, g2p, gp[2 * q + 1]);
            }
        }
        // epilogue for this half: grad += W1[:,i] * (sigmoid(a1_i) * g1_i)
        #pragma unroll
        for (int k = 0; k < 32; k++) {
            int m = half * 32 + k;                  // ull index: i-pair (2m, 2m+1)
            ull w1a = W1p[m], w1b = W1p[64 + m], w1c = W1p[128 + m];
            ull a1 = ffma2(xx, w1a, ffma2(yy, w1b, ffma2(zz, w1c, b1p[m])));
            float alo, ahi; unpack2(a1, alo, ahi);
            float glo, ghi; unpack2(gp[k], glo, ghi);
            ull gi = pack2(glo * sigmoidf(alo), ghi * sigmoidf(ahi));
            gxp = ffma2(w1a, gi, gxp);
            gyp = ffma2(w1b, gi, gyp);
            gzp = ffma2(w1c, gi, gzp);
        }
    }
    float gx, gy, gz, t0, t1;
    unpack2(gxp, t0, t1); gx = t0 + t1;
    unpack2(gyp, t0, t1); gy = t0 + t1;
    unpack2(gzp, t0, t1); gz = t0 + t1;

    int p = r * 128 + s;
    grad_out[3 * p + 0] = gx;
    grad_out[3 * p + 1] = gy;
    grad_out[3 * p + 2] = gz;
    g_tc[s * NR + r] = gx * dx + gy * dy + gz * dz;
}

// ---------------- per-ray upsample + sample_pdf ----------------
__global__ void k_upsample(int S, float inv_s, int flag,
                           const float* __restrict__ ro, const float* __restrict__ rd) {
    int r = blockIdx.x * blockDim.x + threadIdx.x;
    if (r >= NR) return;
    const float* zb = flag ? g_z1 : g_z0;
    const float* fb = flag ? g_s1 : g_s0;
    float ox = ro[3 * r], oy = ro[3 * r + 1], oz = ro[3 * r + 2];
    float dx = rd[3 * r], dy = rd[3 * r + 1], dz = rd[3 * r + 2];

    // pass 1: weights -> g_w, wsum
    float T = 1.f, wsum = 0.f, cprev = 0.f;
    float z0v = zb[r], f0 = fb[r];
    float px = ox + dx * z0v, py = oy + dy * z0v, pz = oz + dz * z0v;
    float rad_prev = sqrtf(px * px + py * py + pz * pz);
    for (int k = 0; k < S - 1; k++) {
        float z1v = zb[(k + 1) * NR + r], f1 = fb[(k + 1) * NR + r];
        float qx = ox + dx * z1v, qy = oy + dy * z1v, qz = oz + dz * z1v;
        float rad_next = sqrtf(qx * qx + qy * qy + qz * qz);
        float inside = (rad_prev < 1.f || rad_next < 1.f) ? 1.f : 0.f;
        rad_prev = rad_next;
        float c = (f1 - f0) / (z1v - z0v + 1e-5f);
        float cc = fminf((k == 0) ? 0.f : cprev, c);
        cprev = c;
        cc = fminf(fmaxf(cc, -1000.f), 0.f) * inside;
        float midv = 0.5f * (f0 + f1);
        float dd = z1v - z0v;
        float pc = sigmoidf((midv - cc * dd * 0.5f) * inv_s);
        float nc = sigmoidf((midv + cc * dd * 0.5f) * inv_s);
        float a = (pc - nc + 1e-5f) / (pc + 1e-5f);
        float wk = a * T + 1e-5f;
        T *= (1.f - a + 1e-7f);
        g_w[k * NR + r] = wk;
        wsum += wk;
        z0v = z1v; f0 = f1;
    }

    // pass 2: cdf walk + inverse-CDF sampling (searchsorted side='right')
    int t = 0;
    float cb = 0.f, run = 0.f;
    z0v = zb[r];
    for (int k = 0; k < S - 1 && t < 16; k++) {
        float z1v = zb[(k + 1) * NR + r];
        run += g_w[k * NR + r] / wsum;
        while (t < 16) {
            float u = (float)(2 * t + 1) * 0.03125f;   // exact (2t+1)/32
            if (!(u < run)) break;
            float denom = run - cb;
            if (denom < 1e-5f) denom = 1.f;
            float tt = (u - cb) / denom;
            g_newz[t * NR + r] = z0v + tt * (z1v - z0v);
            t++;
        }
        cb = run; z0v = z1v;
    }
    float zlast = zb[(S - 1) * NR + r];
    while (t < 16) { g_newz[t * NR + r] = zlast; t++; }
}

// ---------------- per-ray stable merge (streaming, ping-pong) ----------------
__global__ void k_merge(int S, int flag, int last) {
    int r = blockIdx.x * blockDim.x + threadIdx.x;
    if (r >= NR) return;
    const float* zi = flag ? g_z1 : g_z0;
    float* zo = flag ? g_z0 : g_z1;
    const float* si = flag ? g_s1 : g_s0;
    float* so = flag ? g_s0 : g_s1;
    int i = 0, j = 0;
    float zv = zi[r], nv = g_newz[r];
    for (int t = 0; t < S + 16; t++) {
        bool takeold = (j >= 16) || (i < S && zv <= nv);
        if (takeold) {
            zo[t * NR + r] = zv;
            if (!last) so[t * NR + r] = si[i * NR + r];
            i++;
            if (i < S) zv = zi[i * NR + r];
        } else {
            zo[t * NR + r] = nv;
            if (!last) so[t * NR + r] = g_newsdf[j * NR + r];
            j++;
            if (j < 16) nv = g_newz[j * NR + r];
        }
    }
}

// ---------------- per-ray render (depth) ----------------
__global__ void k_render(const float* __restrict__ variance, float* __restrict__ out) {
    int r = blockIdx.x * blockDim.x + threadIdx.x;
    if (r >= NR) return;
    float inv_s = expf(10.f * variance[0]);
    inv_s = fminf(fmaxf(inv_s, 1e-6f), 1e6f);
    float T = 1.f, depth = 0.f;
    for (int k = 0; k < 128; k++) {
        float zk = g_z0[k * NR + r];
        float dist = (k < 127) ? (g_z0[(k + 1) * NR + r] - zk) : 0.03125f;
        float tc = g_tc[k * NR + r];
        float itc = -fmaxf(0.5f - 0.5f * tc, 0.f);   // COS_ANNEAL_RATIO = 0
        float sdf = g_fsdf[k * NR + r];
        float pc = sigmoidf((sdf - itc * dist * 0.5f) * inv_s);
        float nc = sigmoidf((sdf + itc * dist * 0.5f) * inv_s);
        float a = (pc - nc + 1e-5f) / (pc + 1e-5f);
        a = fminf(fmaxf(a, 0.f), 1.f);
        depth += a * T * zk;
        T *= (1.f - a + 1e-7f);
    }
    out[r] = depth;
}

// ---------------- launch ----------------
extern "C" void kernel_launch(void* const* d_in, const int* in_sizes, int n_in,
                              void* d_out, int out_size) {
    const float* rays_o = (const float*)d_in[0];
    const float* rays_d = (const float*)d_in[1];
    const float* near_  = (const float*)d_in[2];
    const float* far_   = (const float*)d_in[3];
    const float* W1 = (const float*)d_in[4];
    const float* b1 = (const float*)d_in[5];
    const float* W2 = (const float*)d_in[6];
    const float* b2 = (const float*)d_in[7];
    const float* W3 = (const float*)d_in[8];
    const float* b3 = (const float*)d_in[9];
    const float* var = (const float*)d_in[10];
    float* out = (float*)d_out;

    cudaFuncSetAttribute(k_mlp_fwd, cudaFuncAttributeMaxDynamicSharedMemorySize, SMEM_FWD);
    cudaFuncSetAttribute(k_mlp_fwdbwd, cudaFuncAttributeMaxDynamicSharedMemorySize, SMEM_BWD);

    // initial coarse sampling: S=64
    k_init_z<<<(NR * 64) / 256, 256>>>(near_, far_);
    k_mlp_fwd<<<(NR * 64) / 256, 256, SMEM_FWD>>>(W1, b1, W2, b2, W3, b3, rays_o, rays_d, 0);

    // 4 upsample rounds, +16 samples each; z/sdf ping-pong
    for (int i = 0; i < 4; i++) {
        int S = 64 + 16 * i;
        float inv_s = (float)(64 << i);
        int flag = i & 1;
        k_upsample<<<NR / 32, 32>>>(S, inv_s, flag, rays_o, rays_d);
        if (i < 3)
            k_mlp_fwd<<<(NR * 16) / 256, 256, SMEM_FWD>>>(W1, b1, W2, b2, W3, b3, rays_o, rays_d, 1);
        k_merge<<<NR / 32, 32>>>(S, flag, (i == 3) ? 1 : 0);
    }

    // final: S=128 (in g_z0), fused forward+backward MLP, then render
    k_mlp_fwdbwd<<<(NR * 128) / 256, 256, SMEM_BWD>>>(W1, b1, W2, b2, W3, b3,
                                                      rays_o, rays_d, out + NR);
    k_render<<<NR / 32, 32>>>(var, out);
}

// round 7
// speedup vs baseline: 1.3560x; 1.0624x over previous
#include <cuda_runtime.h>
#include <math.h>

#define NR 4096
#define MAXS 128
#define STR 132   // padded smem row stride (floats)
typedef unsigned long long ull;

// ---------------- scratch (device globals) ----------------
__device__ float g_z0[NR * MAXS], g_z1[NR * MAXS];   // z ping-pong, layout [s][r]
__device__ float g_s0[NR * MAXS], g_s1[NR * MAXS];   // sdf ping-pong
__device__ float g_newz[NR * 16], g_newsdf[NR * 16]; // [t][r]
__device__ float g_w[NR * MAXS];                     // upsample weights scratch
__device__ float g_fsdf[NR * MAXS], g_tc[NR * MAXS]; // final pass, [s][r]

// ---------------- helpers ----------------
__device__ __forceinline__ ull pack2(float lo, float hi) {
    ull d; asm("mov.b64 %0, {%1, %2};" : "=l"(d) : "f"(lo), "f"(hi)); return d;
}
__device__ __forceinline__ void unpack2(ull v, float& lo, float& hi) {
    asm("mov.b64 {%0, %1}, %2;" : "=f"(lo), "=f"(hi) : "l"(v));
}
__device__ __forceinline__ ull ffma2(ull a, ull b, ull c) {
    ull d; asm("fma.rn.f32x2 %0, %1, %2, %3;" : "=l"(d) : "l"(a), "l"(b), "l"(c)); return d;
}
__device__ __forceinline__ ull fadd2(ull a, ull b) {
    ull d; asm("add.rn.f32x2 %0, %1, %2;" : "=l"(d) : "l"(a), "l"(b)); return d;
}
__device__ __forceinline__ float softplusf(float x) {
    return fmaxf(x, 0.f) + log1pf(expf(-fabsf(x)));
}
__device__ __forceinline__ float sigmoidf(float x) {
    return 1.f / (1.f + expf(-x));
}

// ---------------- init z (linspace, [s][r]) ----------------
__global__ void k_init_z(const float* __restrict__ near_, const float* __restrict__ far_) {
    int idx = blockIdx.x * blockDim.x + threadIdx.x;
    if (idx >= NR * 64) return;
    int r = idx & (NR - 1), s = idx >> 12;
    float t = (s == 63) ? 1.0f : s * (1.0f / 63.0f);
    g_z0[s * NR + r] = near_[r] + (far_[r] - near_[r]) * t;
}

// =====================================================================
// GEMM-structured MLP kernels. Block = 256 threads = 128-point tile.
// Thread (tp = t>>4, tj = t&15): 8 points (8tp..8tp+7 as 4 f32x2 pairs)
// x 8 outputs (j = tj + 16q, q = 0..7).
// =====================================================================

// fwd smem (floats): W2s 16384 | AT 16896 | W1s 384 | b1s 128 | b2s 128 | W3s 128 | xs/ys/zs 3*128
#define SMEM_F  (34432 * 4)
// fwdbwd adds W2Ts 16896 and dxs/dys/dzs 3*128
#define SMEM_B2 (51712 * 4)

__global__ __launch_bounds__(256, 1) void k_mlp_fwd(
    const float* __restrict__ W1, const float* __restrict__ b1,
    const float* __restrict__ W2, const float* __restrict__ b2,
    const float* __restrict__ W3, const float* __restrict__ b3,
    const float* __restrict__ ro, const float* __restrict__ rd,
    int mode)  // 0: z from g_z0 -> g_s0 ; 1: z from g_newz -> g_newsdf
{
    extern __shared__ float sm[];
    float* W2s = sm;
    float* AT  = sm + 16384;
    float* W1s = sm + 33280;
    float* b1s = sm + 33664;
    float* b2s = sm + 33792;
    float* W3s = sm + 33920;
    float* xs  = sm + 34048;
    float* ys  = sm + 34176;
    float* zs  = sm + 34304;
    int t = threadIdx.x;

    for (int e = t; e < 16384; e += 256) W2s[e] = W2[e];
    for (int e = t; e < 384; e += 256) W1s[e] = W1[e];
    if (t < 128) { b1s[t] = b1[t]; b2s[t] = b2[t]; W3s[t] = W3[t]; }
    if (t < 128) {
        int gidx = blockIdx.x * 128 + t;
        int r = gidx & (NR - 1);
        float z = (mode == 0) ? g_z0[gidx] : g_newz[gidx];
        xs[t] = ro[3*r]   + rd[3*r]   * z;
        ys[t] = ro[3*r+1] + rd[3*r+1] * z;
        zs[t] = ro[3*r+2] + rd[3*r+2] * z;
    }
    __syncthreads();

    // stage 1: h1 -> AT[i][p] (thread t: unit i = t>>1, point-half = t&1)
    {
        int i = t >> 1, pb = (t & 1) * 64;
        float w1x = W1s[i], w1y = W1s[128+i], w1z = W1s[256+i], b1i = b1s[i];
        #pragma unroll 4
        for (int p = pb; p < pb + 64; p++) {
            float a = fmaf(xs[p], w1x, fmaf(ys[p], w1y, fmaf(zs[p], w1z, b1i)));
            AT[i * STR + p] = softplusf(a);
        }
    }
    __syncthreads();

    // stage A: a2[p][j] = sum_i h1[p][i] * W2[i][j]
    int tp = t >> 4, tj = t & 15;
    ull acc[4][8];
    #pragma unroll
    for (int pp = 0; pp < 4; pp++)
        #pragma unroll
        for (int q = 0; q < 8; q++) acc[pp][q] = 0;
    const ulonglong2* ATv = (const ulonglong2*)AT;   // AT row i = ull2 index 33i
    #pragma unroll 2
    for (int i = 0; i < 128; i++) {
        ulonglong2 a01 = ATv[i * 33 + 2*tp];
        ulonglong2 a23 = ATv[i * 33 + 2*tp + 1];
        ull ws[8];
        #pragma unroll
        for (int q = 0; q < 8; q++) { float w = W2s[i*128 + tj + 16*q]; ws[q] = pack2(w, w); }
        #pragma unroll
        for (int q = 0; q < 8; q++) {
            acc[0][q] = ffma2(a01.x, ws[q], acc[0][q]);
            acc[1][q] = ffma2(a01.y, ws[q], acc[1][q]);
            acc[2][q] = ffma2(a23.x, ws[q], acc[2][q]);
            acc[3][q] = ffma2(a23.y, ws[q], acc[3][q]);
        }
    }

    // epilogue: sdf = b3 + sum_j softplus(a2+b2)*W3
    ull sdfp[4] = {0, 0, 0, 0};
    #pragma unroll
    for (int q = 0; q < 8; q++) {
        int j = tj + 16*q;
        float b2j = b2s[j], w3j = W3s[j];
        ull w3p = pack2(w3j, w3j);
        #pragma unroll
        for (int pp = 0; pp < 4; pp++) {
            float alo, ahi; unpack2(acc[pp][q], alo, ahi);
            alo += b2j; ahi += b2j;
            sdfp[pp] = ffma2(pack2(softplusf(alo), softplusf(ahi)), w3p, sdfp[pp]);
        }
    }
    #pragma unroll
    for (int m = 1; m < 16; m <<= 1)
        #pragma unroll
        for (int pp = 0; pp < 4; pp++)
            sdfp[pp] = fadd2(sdfp[pp], __shfl_xor_sync(0xffffffffu, sdfp[pp], m, 16));
    if (tj == 0) {
        float b3v = b3[0];
        float* outb = (mode == 0) ? g_s0 : g_newsdf;
        int gb = blockIdx.x * 128 + 8*tp;
        #pragma unroll
        for (int pp = 0; pp < 4; pp++) {
            float lo, hi; unpack2(sdfp[pp], lo, hi);
            outb[gb + 2*pp]     = lo + b3v;
            outb[gb + 2*pp + 1] = hi + b3v;
        }
    }
}

__global__ __launch_bounds__(256, 1) void k_mlp_fwdbwd(
    const float* __restrict__ W1, const float* __restrict__ b1,
    const float* __restrict__ W2, const float* __restrict__ b2,
    const float* __restrict__ W3, const float* __restrict__ b3,
    const float* __restrict__ ro, const float* __restrict__ rd,
    float* __restrict__ grad_out)
{
    extern __shared__ float sm[];
    float* W2s  = sm;
    float* W2Ts = sm + 16384;
    float* ATG  = sm + 33280;   // h1T in stage A, reused as g2T in stage B
    float* W1s = sm + 50176;
    float* b1s = sm + 50560;
    float* b2s = sm + 50688;
    float* W3s = sm + 50816;
    float* xs  = sm + 50944;
    float* ys  = sm + 51072;
    float* zs  = sm + 51200;
    float* dxs = sm + 51328;
    float* dys = sm + 51456;
    float* dzs = sm + 51584;
    int t = threadIdx.x;

    for (int e = t; e < 16384; e += 256) {
        float v = W2[e];
        W2s[e] = v;
        W2Ts[(e & 127) * STR + (e >> 7)] = v;   // W2Ts[j][i]
    }
    for (int e = t; e < 384; e += 256) W1s[e] = W1[e];
    if (t < 128) { b1s[t] = b1[t]; b2s[t] = b2[t]; W3s[t] = W3[t]; }
    if (t < 128) {
        int gidx = blockIdx.x * 128 + t;
        int r = gidx & (NR - 1), s = gidx >> 12;
        float zk = g_z0[gidx];
        float dist = (s < 127) ? (g_z0[gidx + NR] - zk) : 0.03125f;   // SAMPLE_DIST
        float midz = zk + 0.5f * dist;
        float dx = rd[3*r], dy = rd[3*r+1], dz = rd[3*r+2];
        dxs[t] = dx; dys[t] = dy; dzs[t] = dz;
        xs[t] = ro[3*r]   + dx * midz;
        ys[t] = ro[3*r+1] + dy * midz;
        zs[t] = ro[3*r+2] + dz * midz;
    }
    __syncthreads();

    // stage 1: h1 -> ATG[i][p]
    {
        int i = t >> 1, pb = (t & 1) * 64;
        float w1x = W1s[i], w1y = W1s[128+i], w1z = W1s[256+i], b1i = b1s[i];
        #pragma unroll 4
        for (int p = pb; p < pb + 64; p++) {
            float a = fmaf(xs[p], w1x, fmaf(ys[p], w1y, fmaf(zs[p], w1z, b1i)));
            ATG[i * STR + p] = softplusf(a);
        }
    }
    __syncthreads();

    int tp = t >> 4, tj = t & 15;
    // stage A GEMM: a2[p][j]
    ull acc[4][8];
    #pragma unroll
    for (int pp = 0; pp < 4; pp++)
        #pragma unroll
        for (int q = 0; q < 8; q++) acc[pp][q] = 0;
    {
        const ulonglong2* ATv = (const ulonglong2*)ATG;
        #pragma unroll 2
        for (int i = 0; i < 128; i++) {
            ulonglong2 a01 = ATv[i * 33 + 2*tp];
            ulonglong2 a23 = ATv[i * 33 + 2*tp + 1];
            ull ws[8];
            #pragma unroll
            for (int q = 0; q < 8; q++) { float w = W2s[i*128 + tj + 16*q]; ws[q] = pack2(w, w); }
            #pragma unroll
            for (int q = 0; q < 8; q++) {
                acc[0][q] = ffma2(a01.x, ws[q], acc[0][q]);
                acc[1][q] = ffma2(a01.y, ws[q], acc[1][q]);
                acc[2][q] = ffma2(a23.x, ws[q], acc[2][q]);
                acc[3][q] = ffma2(a23.y, ws[q], acc[3][q]);
            }
        }
    }

    // epilogue A: sdf, and overwrite acc with g2 = sigmoid(a2)*W3
    ull sdfp[4] = {0, 0, 0, 0};
    #pragma unroll
    for (int q = 0; q < 8; q++) {
        int j = tj + 16*q;
        float b2j = b2s[j], w3j = W3s[j];
        ull w3p = pack2(w3j, w3j);
        #pragma unroll
        for (int pp = 0; pp < 4; pp++) {
            float alo, ahi; unpack2(acc[pp][q], alo, ahi);
            alo += b2j; ahi += b2j;
            float elo = expf(-fabsf(alo)), ehi = expf(-fabsf(ahi));
            float h2lo = fmaxf(alo, 0.f) + log1pf(elo);
            float h2hi = fmaxf(ahi, 0.f) + log1pf(ehi);
            sdfp[pp] = ffma2(pack2(h2lo, h2hi), w3p, sdfp[pp]);
            float siglo = (alo >= 0.f) ? (1.f / (1.f + elo)) : (elo / (1.f + elo));
            float sighi = (ahi >= 0.f) ? (1.f / (1.f + ehi)) : (ehi / (1.f + ehi));
            acc[pp][q] = pack2(siglo * w3j, sighi * w3j);
        }
    }
    #pragma unroll
    for (int m = 1; m < 16; m <<= 1)
        #pragma unroll
        for (int pp = 0; pp < 4; pp++)
            sdfp[pp] = fadd2(sdfp[pp], __shfl_xor_sync(0xffffffffu, sdfp[pp], m, 16));
    if (tj == 0) {
        float b3v = b3[0];
        int gb = blockIdx.x * 128 + 8*tp;
        #pragma unroll
        for (int pp = 0; pp < 4; pp++) {
            float lo, hi; unpack2(sdfp[pp], lo, hi);
            g_fsdf[gb + 2*pp]     = lo + b3v;
            g_fsdf[gb + 2*pp + 1] = hi + b3v;
        }
    }

    // stash g2 into ATG (transposed [j][p], pair-preserving 64-bit stores)
    __syncthreads();   // everyone done reading h1T
    {
        ull* g2v = (ull*)ATG;
        #pragma unroll
        for (int q = 0; q < 8; q++)
            #pragma unroll
            for (int pp = 0; pp < 4; pp++)
                g2v[(tj + 16*q) * 66 + 4*tp + pp] = acc[pp][q];
    }
    __syncthreads();

    // stage B GEMM: g1[p][i] = sum_j g2[p][j] * W2T[j][i]   (i = ti + 16u, ti = tj)
    int ti = tj;
    ull acc2[4][8];
    #pragma unroll
    for (int pp = 0; pp < 4; pp++)
        #pragma unroll
        for (int u = 0; u < 8; u++) acc2[pp][u] = 0;
    {
        const ulonglong2* G2v = (const ulonglong2*)ATG;
        #pragma unroll 2
        for (int j = 0; j < 128; j++) {
            ulonglong2 g01 = G2v[j * 33 + 2*tp];
            ulonglong2 g23 = G2v[j * 33 + 2*tp + 1];
            ull ws[8];
            #pragma unroll
            for (int u = 0; u < 8; u++) { float w = W2Ts[j*STR + ti + 16*u]; ws[u] = pack2(w, w); }
            #pragma unroll
            for (int u = 0; u < 8; u++) {
                acc2[0][u] = ffma2(g01.x, ws[u], acc2[0][u]);
                acc2[1][u] = ffma2(g01.y, ws[u], acc2[1][u]);
                acc2[2][u] = ffma2(g23.x, ws[u], acc2[2][u]);
                acc2[3][u] = ffma2(g23.y, ws[u], acc2[3][u]);
            }
        }
    }

    // epilogue B: grad = W1 @ (sigmoid(a1) * g1)
    ull xp[4], yp[4], zp[4];
    {
        const ull* xv = (const ull*)xs; const ull* yv = (const ull*)ys; const ull* zv = (const ull*)zs;
        #pragma unroll
        for (int pp = 0; pp < 4; pp++) { xp[pp] = xv[4*tp+pp]; yp[pp] = yv[4*tp+pp]; zp[pp] = zv[4*tp+pp]; }
    }
    ull gx[4] = {0,0,0,0}, gy[4] = {0,0,0,0}, gz[4] = {0,0,0,0};
    #pragma unroll
    for (int u = 0; u < 8; u++) {
        int ii = ti + 16*u;
        float w1x = W1s[ii], w1y = W1s[128+ii], w1z = W1s[256+ii], b1i = b1s[ii];
        ull wxp = pack2(w1x, w1x), wyp = pack2(w1y, w1y), wzp = pack2(w1z, w1z);
        ull b1p = pack2(b1i, b1i);
        #pragma unroll
        for (int pp = 0; pp < 4; pp++) {
            ull a1 = ffma2(xp[pp], wxp, ffma2(yp[pp], wyp, ffma2(zp[pp], wzp, b1p)));
            float alo, ahi; unpack2(a1, alo, ahi);
            float glo, ghi; unpack2(acc2[pp][u], glo, ghi);
            ull gi = pack2(glo * sigmoidf(alo), ghi * sigmoidf(ahi));
            gx[pp] = ffma2(wxp, gi, gx[pp]);
            gy[pp] = ffma2(wyp, gi, gy[pp]);
            gz[pp] = ffma2(wzp, gi, gz[pp]);
        }
    }
    #pragma unroll
    for (int m = 1; m < 16; m <<= 1)
        #pragma unroll
        for (int pp = 0; pp < 4; pp++) {
            gx[pp] = fadd2(gx[pp], __shfl_xor_sync(0xffffffffu, gx[pp], m, 16));
            gy[pp] = fadd2(gy[pp], __shfl_xor_sync(0xffffffffu, gy[pp], m, 16));
            gz[pp] = fadd2(gz[pp], __shfl_xor_sync(0xffffffffu, gz[pp], m, 16));
        }
    if (ti == 0) {
        int gb = blockIdx.x * 128;
        int s = gb >> 12;
        int rb = (gb & (NR - 1));
        #pragma unroll
        for (int pp = 0; pp < 4; pp++) {
            float gxl, gxh, gyl, gyh, gzl, gzh;
            unpack2(gx[pp], gxl, gxh); unpack2(gy[pp], gyl, gyh); unpack2(gz[pp], gzl, gzh);
            int p0 = 8*tp + 2*pp;
            int o0 = 3 * ((rb + p0) * 128 + s);
            grad_out[o0]   = gxl; grad_out[o0+1] = gyl; grad_out[o0+2] = gzl;
            g_tc[gb + p0] = gxl*dxs[p0] + gyl*dys[p0] + gzl*dzs[p0];
            int o1 = 3 * ((rb + p0 + 1) * 128 + s);
            grad_out[o1]   = gxh; grad_out[o1+1] = gyh; grad_out[o1+2] = gzh;
            g_tc[gb + p0 + 1] = gxh*dxs[p0+1] + gyh*dys[p0+1] + gzh*dzs[p0+1];
        }
    }
}

// ---------------- per-ray upsample + sample_pdf ----------------
__global__ void k_upsample(int S, float inv_s, int flag,
                           const float* __restrict__ ro, const float* __restrict__ rd) {
    int r = blockIdx.x * blockDim.x + threadIdx.x;
    if (r >= NR) return;
    const float* zb = flag ? g_z1 : g_z0;
    const float* fb = flag ? g_s1 : g_s0;
    float ox = ro[3 * r], oy = ro[3 * r + 1], oz = ro[3 * r + 2];
    float dx = rd[3 * r], dy = rd[3 * r + 1], dz = rd[3 * r + 2];

    float T = 1.f, wsum = 0.f, cprev = 0.f;
    float z0v = zb[r], f0 = fb[r];
    float px = ox + dx * z0v, py = oy + dy * z0v, pz = oz + dz * z0v;
    float rad_prev = sqrtf(px * px + py * py + pz * pz);
    for (int k = 0; k < S - 1; k++) {
        float z1v = zb[(k + 1) * NR + r], f1 = fb[(k + 1) * NR + r];
        float qx = ox + dx * z1v, qy = oy + dy * z1v, qz = oz + dz * z1v;
        float rad_next = sqrtf(qx * qx + qy * qy + qz * qz);
        float inside = (rad_prev < 1.f || rad_next < 1.f) ? 1.f : 0.f;
        rad_prev = rad_next;
        float c = (f1 - f0) / (z1v - z0v + 1e-5f);
        float cc = fminf((k == 0) ? 0.f : cprev, c);
        cprev = c;
        cc = fminf(fmaxf(cc, -1000.f), 0.f) * inside;
        float midv = 0.5f * (f0 + f1);
        float dd = z1v - z0v;
        float pc = sigmoidf((midv - cc * dd * 0.5f) * inv_s);
        float nc = sigmoidf((midv + cc * dd * 0.5f) * inv_s);
        float a = (pc - nc + 1e-5f) / (pc + 1e-5f);
        float wk = a * T + 1e-5f;
        T *= (1.f - a + 1e-7f);
        g_w[k * NR + r] = wk;
        wsum += wk;
        z0v = z1v; f0 = f1;
    }

    int t = 0;
    float cb = 0.f, run = 0.f;
    z0v = zb[r];
    for (int k = 0; k < S - 1 && t < 16; k++) {
        float z1v = zb[(k + 1) * NR + r];
        run += g_w[k * NR + r] / wsum;
        while (t < 16) {
            float u = (float)(2 * t + 1) * 0.03125f;
            if (!(u < run)) break;
            float denom = run - cb;
            if (denom < 1e-5f) denom = 1.f;
            float tt = (u - cb) / denom;
            g_newz[t * NR + r] = z0v + tt * (z1v - z0v);
            t++;
        }
        cb = run; z0v = z1v;
    }
    float zlast = zb[(S - 1) * NR + r];
    while (t < 16) { g_newz[t * NR + r] = zlast; t++; }
}

// ---------------- per-ray stable merge (streaming, ping-pong) ----------------
__global__ void k_merge(int S, int flag, int last) {
    int r = blockIdx.x * blockDim.x + threadIdx.x;
    if (r >= NR) return;
    const float* zi = flag ? g_z1 : g_z0;
    float* zo = flag ? g_z0 : g_z1;
    const float* si = flag ? g_s1 : g_s0;
    float* so = flag ? g_s0 : g_s1;
    int i = 0, j = 0;
    float zv = zi[r], nv = g_newz[r];
    for (int t = 0; t < S + 16; t++) {
        bool takeold = (j >= 16) || (i < S && zv <= nv);
        if (takeold) {
            zo[t * NR + r] = zv;
            if (!last) so[t * NR + r] = si[i * NR + r];
            i++;
            if (i < S) zv = zi[i * NR + r];
        } else {
            zo[t * NR + r] = nv;
            if (!last) so[t * NR + r] = g_newsdf[j * NR + r];
            j++;
            if (j < 16) nv = g_newz[j * NR + r];
        }
    }
}

// ---------------- per-ray render (depth) ----------------
__global__ void k_render(const float* __restrict__ variance, float* __restrict__ out) {
    int r = blockIdx.x * blockDim.x + threadIdx.x;
    if (r >= NR) return;
    float inv_s = expf(10.f * variance[0]);
    inv_s = fminf(fmaxf(inv_s, 1e-6f), 1e6f);
    float T = 1.f, depth = 0.f;
    for (int k = 0; k < 128; k++) {
        float zk = g_z0[k * NR + r];
        float dist = (k < 127) ? (g_z0[(k + 1) * NR + r] - zk) : 0.03125f;
        float tc = g_tc[k * NR + r];
        float itc = -fmaxf(0.5f - 0.5f * tc, 0.f);   // COS_ANNEAL_RATIO = 0
        float sdf = g_fsdf[k * NR + r];
        float pc = sigmoidf((sdf - itc * dist * 0.5f) * inv_s);
        float nc = sigmoidf((sdf + itc * dist * 0.5f) * inv_s);
        float a = (pc - nc + 1e-5f) / (pc + 1e-5f);
        a = fminf(fmaxf(a, 0.f), 1.f);
        depth += a * T * zk;
        T *= (1.f - a + 1e-7f);
    }
    out[r] = depth;
}

// ---------------- launch ----------------
extern "C" void kernel_launch(void* const* d_in, const int* in_sizes, int n_in,
                              void* d_out, int out_size) {
    const float* rays_o = (const float*)d_in[0];
    const float* rays_d = (const float*)d_in[1];
    const float* near_  = (const float*)d_in[2];
    const float* far_   = (const float*)d_in[3];
    const float* W1 = (const float*)d_in[4];
    const float* b1 = (const float*)d_in[5];
    const float* W2 = (const float*)d_in[6];
    const float* b2 = (const float*)d_in[7];
    const float* W3 = (const float*)d_in[8];
    const float* b3 = (const float*)d_in[9];
    const float* var = (const float*)d_in[10];
    float* out = (float*)d_out;

    cudaFuncSetAttribute(k_mlp_fwd, cudaFuncAttributeMaxDynamicSharedMemorySize, SMEM_F);
    cudaFuncSetAttribute(k_mlp_fwdbwd, cudaFuncAttributeMaxDynamicSharedMemorySize, SMEM_B2);

    // initial coarse sampling: S=64 (262144 points -> 2048 tiles)
    k_init_z<<<(NR * 64) / 256, 256>>>(near_, far_);
    k_mlp_fwd<<<(NR * 64) / 128, 256, SMEM_F>>>(W1, b1, W2, b2, W3, b3, rays_o, rays_d, 0);

    // 4 upsample rounds, +16 samples each; z/sdf ping-pong
    for (int i = 0; i < 4; i++) {
        int S = 64 + 16 * i;
        float inv_s = (float)(64 << i);
        int flag = i & 1;
        k_upsample<<<NR / 32, 32>>>(S, inv_s, flag, rays_o, rays_d);
        if (i < 3)
            k_mlp_fwd<<<(NR * 16) / 128, 256, SMEM_F>>>(W1, b1, W2, b2, W3, b3, rays_o, rays_d, 1);
        k_merge<<<NR / 32, 32>>>(S, flag, (i == 3) ? 1 : 0);
    }

    // final: S=128 (524288 points -> 4096 tiles), fused fwd+bwd, then render
    k_mlp_fwdbwd<<<(NR * 128) / 128, 256, SMEM_B2>>>(W1, b1, W2, b2, W3, b3,
                                                     rays_o, rays_d, out + NR);
    k_render<<<NR / 32, 32>>>(var, out);
}

// round 8
// speedup vs baseline: 1.5034x; 1.1087x over previous
#include <cuda_runtime.h>
#include <math.h>

#define NR 4096
#define MAXS 128
typedef unsigned long long ull;

// ---------------- scratch (device globals) ----------------
__device__ float g_z0[NR * MAXS], g_z1[NR * MAXS];   // z ping-pong, layout [s][r]
__device__ float g_s0[NR * MAXS], g_s1[NR * MAXS];   // sdf ping-pong
__device__ float g_newz[NR * 16], g_newsdf[NR * 16]; // [t][r]
__device__ float g_w[NR * MAXS];                     // upsample weights scratch
__device__ float g_fsdf[NR * MAXS], g_tc[NR * MAXS]; // final pass, [s][r]
__device__ float g_g2[NR * MAXS * 128];              // g2 per final point, [tile][p][j]

// ---------------- helpers ----------------
__device__ __forceinline__ ull pack2(float lo, float hi) {
    ull d; asm("mov.b64 %0, {%1, %2};" : "=l"(d) : "f"(lo), "f"(hi)); return d;
}
__device__ __forceinline__ void unpack2(ull v, float& lo, float& hi) {
    asm("mov.b64 {%0, %1}, %2;" : "=f"(lo), "=f"(hi) : "l"(v));
}
__device__ __forceinline__ ull ffma2(ull a, ull b, ull c) {
    ull d; asm("fma.rn.f32x2 %0, %1, %2, %3;" : "=l"(d) : "l"(a), "l"(b), "l"(c)); return d;
}
__device__ __forceinline__ ull fadd2(ull a, ull b) {
    ull d; asm("add.rn.f32x2 %0, %1, %2;" : "=l"(d) : "l"(a), "l"(b)); return d;
}
__device__ __forceinline__ float softplusf(float x) {
    return fmaxf(x, 0.f) + log1pf(expf(-fabsf(x)));
}
__device__ __forceinline__ float sigmoidf(float x) {
    return 1.f / (1.f + expf(-x));
}

// ---------------- init z (linspace, [s][r]) ----------------
__global__ void k_init_z(const float* __restrict__ near_, const float* __restrict__ far_) {
    int idx = blockIdx.x * blockDim.x + threadIdx.x;
    if (idx >= NR * 64) return;
    int r = idx & (NR - 1), s = idx >> 12;
    float t = (s == 63) ? 1.0f : s * (1.0f / 63.0f);
    g_z0[s * NR + r] = near_[r] + (far_[r] - near_[r]) * t;
}

// =====================================================================
// GEMM-structured MLP kernels, 2 blocks/SM.
// Block = 256 threads = 128-point tile. Thread (tp=t>>4, tj=t&15):
// 8 points (4 f32x2 pairs) x 8 outputs (j = tj+16q).
// h1 staged in a 64-row chunk buffer (i-chunked) to fit 2 blocks/SM.
// =====================================================================

// fwd smem floats: W2s 16384 | ATc 64*132 | W1s 384 | b1s/b2s/W3s 3*128 | xs/ys/zs 3*128
#define SMEM_F   (25984 * 4)
// bwd smem floats: W2Ts 128*132 | G2c 64*132 | W1s 384 | b1s 128 | xs/ys/zs/dxs/dys/dzs 6*128
#define SMEM_BWD (26624 * 4)

// stage 1 chunk: h1 for i in [64c, 64c+64) -> ATc[i_loc][p], conflict-free
__device__ __forceinline__ void stage1_chunk(
    int c, int t, float* ATc, const float* W1s, const float* b1s,
    const float* xs, const float* ys, const float* zs)
{
    int p = t & 127, ih = t >> 7;
    float xv = xs[p], yv = ys[p], zv = zs[p];
    #pragma unroll 4
    for (int il = 32 * ih; il < 32 * ih + 32; il++) {
        int i = 64 * c + il;
        float a = fmaf(xv, W1s[i], fmaf(yv, W1s[128 + i], fmaf(zv, W1s[256 + i], b1s[i])));
        ATc[il * 132 + p] = softplusf(a);
    }
}

// GEMM chunk: acc[p][j] += sum_{i in chunk} h1[p][i] * W2[i][j]
__device__ __forceinline__ void gemm_chunk(
    int c, int tp, int tj, const float* ATc, const float* W2s, ull acc[4][8])
{
    const ulonglong2* ATv = (const ulonglong2*)ATc;
    #pragma unroll 2
    for (int il = 0; il < 64; il++) {
        int i = 64 * c + il;
        ulonglong2 a01 = ATv[il * 33 + 2 * tp];
        ulonglong2 a23 = ATv[il * 33 + 2 * tp + 1];
        ull ws[8];
        #pragma unroll
        for (int q = 0; q < 8; q++) { float w = W2s[i * 128 + tj + 16 * q]; ws[q] = pack2(w, w); }
        #pragma unroll
        for (int q = 0; q < 8; q++) {
            acc[0][q] = ffma2(a01.x, ws[q], acc[0][q]);
            acc[1][q] = ffma2(a01.y, ws[q], acc[1][q]);
            acc[2][q] = ffma2(a23.x, ws[q], acc[2][q]);
            acc[3][q] = ffma2(a23.y, ws[q], acc[3][q]);
        }
    }
}

__global__ __launch_bounds__(256, 2) void k_mlp_fwd(
    const float* __restrict__ W1, const float* __restrict__ b1,
    const float* __restrict__ W2, const float* __restrict__ b2,
    const float* __restrict__ W3, const float* __restrict__ b3,
    const float* __restrict__ ro, const float* __restrict__ rd,
    int mode)  // 0: z from g_z0 -> g_s0 ; 1: z from g_newz -> g_newsdf
{
    extern __shared__ float sm[];
    float* W2s = sm;
    float* ATc = sm + 16384;
    float* W1s = sm + 24832;
    float* b1s = sm + 25216;
    float* b2s = sm + 25344;
    float* W3s = sm + 25472;
    float* xs  = sm + 25600;
    float* ys  = sm + 25728;
    float* zs  = sm + 25856;
    int t = threadIdx.x;

    for (int e = t; e < 16384; e += 256) W2s[e] = W2[e];
    for (int e = t; e < 384; e += 256) W1s[e] = W1[e];
    if (t < 128) { b1s[t] = b1[t]; b2s[t] = b2[t]; W3s[t] = W3[t]; }
    if (t < 128) {
        int gidx = blockIdx.x * 128 + t;
        int r = gidx & (NR - 1);
        float z = (mode == 0) ? g_z0[gidx] : g_newz[gidx];
        xs[t] = ro[3*r]   + rd[3*r]   * z;
        ys[t] = ro[3*r+1] + rd[3*r+1] * z;
        zs[t] = ro[3*r+2] + rd[3*r+2] * z;
    }
    __syncthreads();

    int tp = t >> 4, tj = t & 15;
    ull acc[4][8];
    #pragma unroll
    for (int pp = 0; pp < 4; pp++)
        #pragma unroll
        for (int q = 0; q < 8; q++) acc[pp][q] = 0;

    #pragma unroll 1
    for (int c = 0; c < 2; c++) {
        if (c) __syncthreads();
        stage1_chunk(c, t, ATc, W1s, b1s, xs, ys, zs);
        __syncthreads();
        gemm_chunk(c, tp, tj, ATc, W2s, acc);
    }

    // epilogue: sdf = b3 + sum_j softplus(a2+b2)*W3
    ull sdfp[4] = {0, 0, 0, 0};
    #pragma unroll
    for (int q = 0; q < 8; q++) {
        int j = tj + 16*q;
        float b2j = b2s[j], w3j = W3s[j];
        ull w3p = pack2(w3j, w3j);
        #pragma unroll
        for (int pp = 0; pp < 4; pp++) {
            float alo, ahi; unpack2(acc[pp][q], alo, ahi);
            alo += b2j; ahi += b2j;
            sdfp[pp] = ffma2(pack2(softplusf(alo), softplusf(ahi)), w3p, sdfp[pp]);
        }
    }
    #pragma unroll
    for (int m = 1; m < 16; m <<= 1)
        #pragma unroll
        for (int pp = 0; pp < 4; pp++)
            sdfp[pp] = fadd2(sdfp[pp], __shfl_xor_sync(0xffffffffu, sdfp[pp], m, 16));
    if (tj == 0) {
        float b3v = b3[0];
        float* outb = (mode == 0) ? g_s0 : g_newsdf;
        int gb = blockIdx.x * 128 + 8*tp;
        #pragma unroll
        for (int pp = 0; pp < 4; pp++) {
            float lo, hi; unpack2(sdfp[pp], lo, hi);
            outb[gb + 2*pp]     = lo + b3v;
            outb[gb + 2*pp + 1] = hi + b3v;
        }
    }
}

// forward for final points (midpoints): writes g_fsdf and g2 -> g_g2 [tile][p][j]
__global__ __launch_bounds__(256, 2) void k_mlp_fwd_g2(
    const float* __restrict__ W1, const float* __restrict__ b1,
    const float* __restrict__ W2, const float* __restrict__ b2,
    const float* __restrict__ W3, const float* __restrict__ b3,
    const float* __restrict__ ro, const float* __restrict__ rd)
{
    extern __shared__ float sm[];
    float* W2s = sm;
    float* ATc = sm + 16384;
    float* W1s = sm + 24832;
    float* b1s = sm + 25216;
    float* b2s = sm + 25344;
    float* W3s = sm + 25472;
    float* xs  = sm + 25600;
    float* ys  = sm + 25728;
    float* zs  = sm + 25856;
    int t = threadIdx.x;

    for (int e = t; e < 16384; e += 256) W2s[e] = W2[e];
    for (int e = t; e < 384; e += 256) W1s[e] = W1[e];
    if (t < 128) { b1s[t] = b1[t]; b2s[t] = b2[t]; W3s[t] = W3[t]; }
    if (t < 128) {
        int gidx = blockIdx.x * 128 + t;
        int r = gidx & (NR - 1), s = gidx >> 12;
        float zk = g_z0[gidx];
        float dist = (s < 127) ? (g_z0[gidx + NR] - zk) : 0.03125f;   // SAMPLE_DIST
        float midz = zk + 0.5f * dist;
        xs[t] = ro[3*r]   + rd[3*r]   * midz;
        ys[t] = ro[3*r+1] + rd[3*r+1] * midz;
        zs[t] = ro[3*r+2] + rd[3*r+2] * midz;
    }
    __syncthreads();

    int tp = t >> 4, tj = t & 15;
    ull acc[4][8];
    #pragma unroll
    for (int pp = 0; pp < 4; pp++)
        #pragma unroll
        for (int q = 0; q < 8; q++) acc[pp][q] = 0;

    #pragma unroll 1
    for (int c = 0; c < 2; c++) {
        if (c) __syncthreads();
        stage1_chunk(c, t, ATc, W1s, b1s, xs, ys, zs);
        __syncthreads();
        gemm_chunk(c, tp, tj, ATc, W2s, acc);
    }

    // epilogue: sdf + g2 store
    float* g2out = g_g2 + (size_t)blockIdx.x * 16384;
    ull sdfp[4] = {0, 0, 0, 0};
    #pragma unroll
    for (int q = 0; q < 8; q++) {
        int j = tj + 16*q;
        float b2j = b2s[j], w3j = W3s[j];
        ull w3p = pack2(w3j, w3j);
        #pragma unroll
        for (int pp = 0; pp < 4; pp++) {
            float alo, ahi; unpack2(acc[pp][q], alo, ahi);
            alo += b2j; ahi += b2j;
            float elo = expf(-fabsf(alo)), ehi = expf(-fabsf(ahi));
            float h2lo = fmaxf(alo, 0.f) + log1pf(elo);
            float h2hi = fmaxf(ahi, 0.f) + log1pf(ehi);
            sdfp[pp] = ffma2(pack2(h2lo, h2hi), w3p, sdfp[pp]);
            float siglo = (alo >= 0.f) ? (1.f / (1.f + elo)) : (elo / (1.f + elo));
            float sighi = (ahi >= 0.f) ? (1.f / (1.f + ehi)) : (ehi / (1.f + ehi));
            int p0 = 8*tp + 2*pp;
            g2out[p0 * 128 + j]       = siglo * w3j;
            g2out[(p0 + 1) * 128 + j] = sighi * w3j;
        }
    }
    #pragma unroll
    for (int m = 1; m < 16; m <<= 1)
        #pragma unroll
        for (int pp = 0; pp < 4; pp++)
            sdfp[pp] = fadd2(sdfp[pp], __shfl_xor_sync(0xffffffffu, sdfp[pp], m, 16));
    if (tj == 0) {
        float b3v = b3[0];
        int gb = blockIdx.x * 128 + 8*tp;
        #pragma unroll
        for (int pp = 0; pp < 4; pp++) {
            float lo, hi; unpack2(sdfp[pp], lo, hi);
            g_fsdf[gb + 2*pp]     = lo + b3v;
            g_fsdf[gb + 2*pp + 1] = hi + b3v;
        }
    }
}

// backward: g1 = g2 @ W2^T, grad = W1 @ (sigmoid(a1)*g1)
__global__ __launch_bounds__(256, 2) void k_mlp_bwd(
    const float* __restrict__ W1, const float* __restrict__ b1,
    const float* __restrict__ W2,
    const float* __restrict__ ro, const float* __restrict__ rd,
    float* __restrict__ grad_out)
{
    extern __shared__ float sm[];
    float* W2Ts = sm;              // [j][i], stride 132
    float* G2c  = sm + 16896;      // 64-row chunk [j_loc][p], stride 132
    float* W1s  = sm + 25344;
    float* b1s  = sm + 25728;
    float* xs   = sm + 25856;
    float* ys   = sm + 25984;
    float* zs   = sm + 26112;
    float* dxs  = sm + 26240;
    float* dys  = sm + 26368;
    float* dzs  = sm + 26496;
    int t = threadIdx.x;

    for (int e = t; e < 16384; e += 256) W2Ts[(e & 127) * 132 + (e >> 7)] = W2[e];
    for (int e = t; e < 384; e += 256) W1s[e] = W1[e];
    if (t < 128) b1s[t] = b1[t];
    if (t < 128) {
        int gidx = blockIdx.x * 128 + t;
        int r = gidx & (NR - 1), s = gidx >> 12;
        float zk = g_z0[gidx];
        float dist = (s < 127) ? (g_z0[gidx + NR] - zk) : 0.03125f;
        float midz = zk + 0.5f * dist;
        float dx = rd[3*r], dy = rd[3*r+1], dz = rd[3*r+2];
        dxs[t] = dx; dys[t] = dy; dzs[t] = dz;
        xs[t] = ro[3*r]   + dx * midz;
        ys[t] = ro[3*r+1] + dy * midz;
        zs[t] = ro[3*r+2] + dz * midz;
    }

    int tp = t >> 4, tj = t & 15, ti = tj;
    const float* g2in = g_g2 + (size_t)blockIdx.x * 16384;
    ull acc2[4][8];
    #pragma unroll
    for (int pp = 0; pp < 4; pp++)
        #pragma unroll
        for (int u = 0; u < 8; u++) acc2[pp][u] = 0;

    #pragma unroll 1
    for (int c = 0; c < 2; c++) {
        __syncthreads();   // covers init loads (c=0) / chunk readers done (c=1)
        for (int e = t; e < 8192; e += 256) {
            int p = e >> 6, jl = e & 63;
            G2c[jl * 132 + p] = g2in[p * 128 + 64 * c + jl];
        }
        __syncthreads();
        const ulonglong2* G2v = (const ulonglong2*)G2c;
        #pragma unroll 2
        for (int jl = 0; jl < 64; jl++) {
            int j = 64 * c + jl;
            ulonglong2 g01 = G2v[jl * 33 + 2*tp];
            ulonglong2 g23 = G2v[jl * 33 + 2*tp + 1];
            ull ws[8];
            #pragma unroll
            for (int u = 0; u < 8; u++) { float w = W2Ts[j * 132 + ti + 16*u]; ws[u] = pack2(w, w); }
            #pragma unroll
            for (int u = 0; u < 8; u++) {
                acc2[0][u] = ffma2(g01.x, ws[u], acc2[0][u]);
                acc2[1][u] = ffma2(g01.y, ws[u], acc2[1][u]);
                acc2[2][u] = ffma2(g23.x, ws[u], acc2[2][u]);
                acc2[3][u] = ffma2(g23.y, ws[u], acc2[3][u]);
            }
        }
    }

    // epilogue: grad = W1 @ (sigmoid(a1) * g1)
    ull xp[4], yp[4], zp[4];
    {
        const ull* xv = (const ull*)xs; const ull* yv = (const ull*)ys; const ull* zv = (const ull*)zs;
        #pragma unroll
        for (int pp = 0; pp < 4; pp++) { xp[pp] = xv[4*tp+pp]; yp[pp] = yv[4*tp+pp]; zp[pp] = zv[4*tp+pp]; }
    }
    ull gx[4] = {0,0,0,0}, gy[4] = {0,0,0,0}, gz[4] = {0,0,0,0};
    #pragma unroll
    for (int u = 0; u < 8; u++) {
        int ii = ti + 16*u;
        float w1x = W1s[ii], w1y = W1s[128+ii], w1z = W1s[256+ii], b1i = b1s[ii];
        ull wxp = pack2(w1x, w1x), wyp = pack2(w1y, w1y), wzp = pack2(w1z, w1z);
        ull b1p = pack2(b1i, b1i);
        #pragma unroll
        for (int pp = 0; pp < 4; pp++) {
            ull a1 = ffma2(xp[pp], wxp, ffma2(yp[pp], wyp, ffma2(zp[pp], wzp, b1p)));
            float alo, ahi; unpack2(a1, alo, ahi);
            float glo, ghi; unpack2(acc2[pp][u], glo, ghi);
            ull gi = pack2(glo * sigmoidf(alo), ghi * sigmoidf(ahi));
            gx[pp] = ffma2(wxp, gi, gx[pp]);
            gy[pp] = ffma2(wyp, gi, gy[pp]);
            gz[pp] = ffma2(wzp, gi, gz[pp]);
        }
    }
    #pragma unroll
    for (int m = 1; m < 16; m <<= 1)
        #pragma unroll
        for (int pp = 0; pp < 4; pp++) {
            gx[pp] = fadd2(gx[pp], __shfl_xor_sync(0xffffffffu, gx[pp], m, 16));
            gy[pp] = fadd2(gy[pp], __shfl_xor_sync(0xffffffffu, gy[pp], m, 16));
            gz[pp] = fadd2(gz[pp], __shfl_xor_sync(0xffffffffu, gz[pp], m, 16));
        }
    if (ti == 0) {
        int gb = blockIdx.x * 128;
        int s = gb >> 12;
        int rb = (gb & (NR - 1));
        #pragma unroll
        for (int pp = 0; pp < 4; pp++) {
            float gxl, gxh, gyl, gyh, gzl, gzh;
            unpack2(gx[pp], gxl, gxh); unpack2(gy[pp], gyl, gyh); unpack2(gz[pp], gzl, gzh);
            int p0 = 8*tp + 2*pp;
            int o0 = 3 * ((rb + p0) * 128 + s);
            grad_out[o0]   = gxl; grad_out[o0+1] = gyl; grad_out[o0+2] = gzl;
            g_tc[gb + p0] = gxl*dxs[p0] + gyl*dys[p0] + gzl*dzs[p0];
            int o1 = 3 * ((rb + p0 + 1) * 128 + s);
            grad_out[o1]   = gxh; grad_out[o1+1] = gyh; grad_out[o1+2] = gzh;
            g_tc[gb + p0 + 1] = gxh*dxs[p0+1] + gyh*dys[p0+1] + gzh*dzs[p0+1];
        }
    }
}

// ---------------- per-ray upsample + sample_pdf ----------------
__global__ void k_upsample(int S, float inv_s, int flag,
                           const float* __restrict__ ro, const float* __restrict__ rd) {
    int r = blockIdx.x * blockDim.x + threadIdx.x;
    if (r >= NR) return;
    const float* zb = flag ? g_z1 : g_z0;
    const float* fb = flag ? g_s1 : g_s0;
    float ox = ro[3 * r], oy = ro[3 * r + 1], oz = ro[3 * r + 2];
    float dx = rd[3 * r], dy = rd[3 * r + 1], dz = rd[3 * r + 2];

    float T = 1.f, wsum = 0.f, cprev = 0.f;
    float z0v = zb[r], f0 = fb[r];
    float px = ox + dx * z0v, py = oy + dy * z0v, pz = oz + dz * z0v;
    float rad_prev = sqrtf(px * px + py * py + pz * pz);
    for (int k = 0; k < S - 1; k++) {
        float z1v = zb[(k + 1) * NR + r], f1 = fb[(k + 1) * NR + r];
        float qx = ox + dx * z1v, qy = oy + dy * z1v, qz = oz + dz * z1v;
        float rad_next = sqrtf(qx * qx + qy * qy + qz * qz);
        float inside = (rad_prev < 1.f || rad_next < 1.f) ? 1.f : 0.f;
        rad_prev = rad_next;
        float c = (f1 - f0) / (z1v - z0v + 1e-5f);
        float cc = fminf((k == 0) ? 0.f : cprev, c);
        cprev = c;
        cc = fminf(fmaxf(cc, -1000.f), 0.f) * inside;
        float midv = 0.5f * (f0 + f1);
        float dd = z1v - z0v;
        float pc = sigmoidf((midv - cc * dd * 0.5f) * inv_s);
        float nc = sigmoidf((midv + cc * dd * 0.5f) * inv_s);
        float a = (pc - nc + 1e-5f) / (pc + 1e-5f);
        float wk = a * T + 1e-5f;
        T *= (1.f - a + 1e-7f);
        g_w[k * NR + r] = wk;
        wsum += wk;
        z0v = z1v; f0 = f1;
    }

    int t = 0;
    float cb = 0.f, run = 0.f;
    z0v = zb[r];
    for (int k = 0; k < S - 1 && t < 16; k++) {
        float z1v = zb[(k + 1) * NR + r];
        run += g_w[k * NR + r] / wsum;
        while (t < 16) {
            float u = (float)(2 * t + 1) * 0.03125f;
            if (!(u < run)) break;
            float denom = run - cb;
            if (denom < 1e-5f) denom = 1.f;
            float tt = (u - cb) / denom;
            g_newz[t * NR + r] = z0v + tt * (z1v - z0v);
            t++;
        }
        cb = run; z0v = z1v;
    }
    float zlast = zb[(S - 1) * NR + r];
    while (t < 16) { g_newz[t * NR + r] = zlast; t++; }
}

// ---------------- per-ray stable merge (streaming, ping-pong) ----------------
__global__ void k_merge(int S, int flag, int last) {
    int r = blockIdx.x * blockDim.x + threadIdx.x;
    if (r >= NR) return;
    const float* zi = flag ? g_z1 : g_z0;
    float* zo = flag ? g_z0 : g_z1;
    const float* si = flag ? g_s1 : g_s0;
    float* so = flag ? g_s0 : g_s1;
    int i = 0, j = 0;
    float zv = zi[r], nv = g_newz[r];
    for (int t = 0; t < S + 16; t++) {
        bool takeold = (j >= 16) || (i < S && zv <= nv);
        if (takeold) {
            zo[t * NR + r] = zv;
            if (!last) so[t * NR + r] = si[i * NR + r];
            i++;
            if (i < S) zv = zi[i * NR + r];
        } else {
            zo[t * NR + r] = nv;
            if (!last) so[t * NR + r] = g_newsdf[j * NR + r];
            j++;
            if (j < 16) nv = g_newz[j * NR + r];
        }
    }
}

// ---------------- per-ray render (depth) ----------------
__global__ void k_render(const float* __restrict__ variance, float* __restrict__ out) {
    int r = blockIdx.x * blockDim.x + threadIdx.x;
    if (r >= NR) return;
    float inv_s = expf(10.f * variance[0]);
    inv_s = fminf(fmaxf(inv_s, 1e-6f), 1e6f);
    float T = 1.f, depth = 0.f;
    for (int k = 0; k < 128; k++) {
        float zk = g_z0[k * NR + r];
        float dist = (k < 127) ? (g_z0[(k + 1) * NR + r] - zk) : 0.03125f;
        float tc = g_tc[k * NR + r];
        float itc = -fmaxf(0.5f - 0.5f * tc, 0.f);   // COS_ANNEAL_RATIO = 0
        float sdf = g_fsdf[k * NR + r];
        float pc = sigmoidf((sdf - itc * dist * 0.5f) * inv_s);
        float nc = sigmoidf((sdf + itc * dist * 0.5f) * inv_s);
        float a = (pc - nc + 1e-5f) / (pc + 1e-5f);
        a = fminf(fmaxf(a, 0.f), 1.f);
        depth += a * T * zk;
        T *= (1.f - a + 1e-7f);
    }
    out[r] = depth;
}

// ---------------- launch ----------------
extern "C" void kernel_launch(void* const* d_in, const int* in_sizes, int n_in,
                              void* d_out, int out_size) {
    const float* rays_o = (const float*)d_in[0];
    const float* rays_d = (const float*)d_in[1];
    const float* near_  = (const float*)d_in[2];
    const float* far_   = (const float*)d_in[3];
    const float* W1 = (const float*)d_in[4];
    const float* b1 = (const float*)d_in[5];
    const float* W2 = (const float*)d_in[6];
    const float* b2 = (const float*)d_in[7];
    const float* W3 = (const float*)d_in[8];
    const float* b3 = (const float*)d_in[9];
    const float* var = (const float*)d_in[10];
    float* out = (float*)d_out;

    cudaFuncSetAttribute(k_mlp_fwd,    cudaFuncAttributeMaxDynamicSharedMemorySize, SMEM_F);
    cudaFuncSetAttribute(k_mlp_fwd_g2, cudaFuncAttributeMaxDynamicSharedMemorySize, SMEM_F);
    cudaFuncSetAttribute(k_mlp_bwd,    cudaFuncAttributeMaxDynamicSharedMemorySize, SMEM_BWD);

    // initial coarse sampling: S=64 (262144 points -> 2048 tiles)
    k_init_z<<<(NR * 64) / 256, 256>>>(near_, far_);
    k_mlp_fwd<<<(NR * 64) / 128, 256, SMEM_F>>>(W1, b1, W2, b2, W3, b3, rays_o, rays_d, 0);

    // 4 upsample rounds, +16 samples each; z/sdf ping-pong
    for (int i = 0; i < 4; i++) {
        int S = 64 + 16 * i;
        float inv_s = (float)(64 << i);
        int flag = i & 1;
        k_upsample<<<NR / 32, 32>>>(S, inv_s, flag, rays_o, rays_d);
        if (i < 3)
            k_mlp_fwd<<<(NR * 16) / 128, 256, SMEM_F>>>(W1, b1, W2, b2, W3, b3, rays_o, rays_d, 1);
        k_merge<<<NR / 32, 32>>>(S, flag, (i == 3) ? 1 : 0);
    }

    // final: S=128 (524288 points -> 4096 tiles): fwd(+g2), bwd, render
    k_mlp_fwd_g2<<<(NR * 128) / 128, 256, SMEM_F>>>(W1, b1, W2, b2, W3, b3, rays_o, rays_d);
    k_mlp_bwd<<<(NR * 128) / 128, 256, SMEM_BWD>>>(W1, b1, W2, rays_o, rays_d, out + NR);
    k_render<<<NR / 32, 32>>>(var, out);
}